// round 1
// baseline (speedup 1.0000x reference)
#include <cuda_runtime.h>
#include <math.h>

#define NB 2
#define NH 12
#define SQ 2048
#define HD 64
#define DM 768

// ---------------- scratch (device globals; no allocations allowed) ----------
__device__ float g_q[NB * NH * SQ * HD];     // (B,H,S,D)
__device__ float g_k[NB * NH * SQ * HD];
__device__ float g_v[NB * NH * SQ * HD];
__device__ float g_attn[NB * SQ * DM];       // (B,S,H*D) row-major

// ---------------------------------------------------------------------------
// QKV projection: y = x @ W^T, written directly into (B,H,S,D) layout.
// BM=128, BN=64 (one head), BK=16, 256 threads, 8x4 per-thread tile.
// gridDim = (12, 32, 3); z selects Wq/Wk/Wv.
// ---------------------------------------------------------------------------
__global__ void qkv_kernel(const float* __restrict__ x,
                           const float* __restrict__ Wq,
                           const float* __restrict__ Wk,
                           const float* __restrict__ Wv) {
    const float* W = (blockIdx.z == 0) ? Wq : (blockIdx.z == 1) ? Wk : Wv;
    float* outp    = (blockIdx.z == 0) ? g_q : (blockIdx.z == 1) ? g_k : g_v;

    __shared__ __align__(16) float As[16][132];   // [k][m], padded
    __shared__ __align__(16) float Bs[16][68];    // [k][n], padded

    int tid = threadIdx.x;
    int ty = tid >> 4;        // 0..15 -> m sub-tile (8 rows)
    int tx = tid & 15;        // 0..15 -> n sub-tile (4 cols)
    int m0 = blockIdx.y * 128;
    int h  = blockIdx.x;      // head == n-tile (BN=64=HD)

    const float* Ab = x + (size_t)m0 * DM;
    const float* Wb = W + (size_t)h * HD * DM;

    float acc[8][4];
#pragma unroll
    for (int i = 0; i < 8; i++)
#pragma unroll
        for (int j = 0; j < 4; j++) acc[i][j] = 0.0f;

    for (int k0 = 0; k0 < DM; k0 += 16) {
#pragma unroll
        for (int i = 0; i < 2; i++) {
            int idx = tid + i * 256;          // 0..511 float4 slots
            int m   = idx >> 2;               // 0..127
            int k4  = (idx & 3) << 2;         // 0,4,8,12
            float4 v = *(const float4*)(Ab + (size_t)m * DM + k0 + k4);
            As[k4 + 0][m] = v.x; As[k4 + 1][m] = v.y;
            As[k4 + 2][m] = v.z; As[k4 + 3][m] = v.w;
        }
        {
            int n  = tid >> 2;                // 0..63
            int k4 = (tid & 3) << 2;
            float4 v = *(const float4*)(Wb + (size_t)n * DM + k0 + k4);
            Bs[k4 + 0][n] = v.x; Bs[k4 + 1][n] = v.y;
            Bs[k4 + 2][n] = v.z; Bs[k4 + 3][n] = v.w;
        }
        __syncthreads();
#pragma unroll
        for (int kk = 0; kk < 16; kk++) {
            float a[8], b[4];
            *(float4*)(a)     = *(const float4*)&As[kk][ty * 8];
            *(float4*)(a + 4) = *(const float4*)&As[kk][ty * 8 + 4];
            *(float4*)(b)     = *(const float4*)&Bs[kk][tx * 4];
#pragma unroll
            for (int i = 0; i < 8; i++)
#pragma unroll
                for (int j = 0; j < 4; j++)
                    acc[i][j] = fmaf(a[i], b[j], acc[i][j]);
        }
        __syncthreads();
    }

#pragma unroll
    for (int i = 0; i < 8; i++) {
        int m = m0 + ty * 8 + i;
        int b = m >> 11;            // /2048
        int s = m & 2047;
        float4 v = make_float4(acc[i][0], acc[i][1], acc[i][2], acc[i][3]);
        *(float4*)&outp[((size_t)(b * NH + h) * SQ + s) * HD + tx * 4] = v;
    }
}

// ---------------------------------------------------------------------------
// Output projection: out = attn(4096,768) @ Wo^T. Same tiling, row-major out.
// ---------------------------------------------------------------------------
__global__ void outproj_kernel(const float* __restrict__ Wo,
                               float* __restrict__ out) {
    __shared__ __align__(16) float As[16][132];
    __shared__ __align__(16) float Bs[16][68];

    int tid = threadIdx.x;
    int ty = tid >> 4, tx = tid & 15;
    int m0 = blockIdx.y * 128;
    int n0 = blockIdx.x * 64;

    const float* Ab = g_attn + (size_t)m0 * DM;
    const float* Wb = Wo + (size_t)n0 * DM;

    float acc[8][4];
#pragma unroll
    for (int i = 0; i < 8; i++)
#pragma unroll
        for (int j = 0; j < 4; j++) acc[i][j] = 0.0f;

    for (int k0 = 0; k0 < DM; k0 += 16) {
#pragma unroll
        for (int i = 0; i < 2; i++) {
            int idx = tid + i * 256;
            int m   = idx >> 2;
            int k4  = (idx & 3) << 2;
            float4 v = *(const float4*)(Ab + (size_t)m * DM + k0 + k4);
            As[k4 + 0][m] = v.x; As[k4 + 1][m] = v.y;
            As[k4 + 2][m] = v.z; As[k4 + 3][m] = v.w;
        }
        {
            int n  = tid >> 2;
            int k4 = (tid & 3) << 2;
            float4 v = *(const float4*)(Wb + (size_t)n * DM + k0 + k4);
            Bs[k4 + 0][n] = v.x; Bs[k4 + 1][n] = v.y;
            Bs[k4 + 2][n] = v.z; Bs[k4 + 3][n] = v.w;
        }
        __syncthreads();
#pragma unroll
        for (int kk = 0; kk < 16; kk++) {
            float a[8], b[4];
            *(float4*)(a)     = *(const float4*)&As[kk][ty * 8];
            *(float4*)(a + 4) = *(const float4*)&As[kk][ty * 8 + 4];
            *(float4*)(b)     = *(const float4*)&Bs[kk][tx * 4];
#pragma unroll
            for (int i = 0; i < 8; i++)
#pragma unroll
                for (int j = 0; j < 4; j++)
                    acc[i][j] = fmaf(a[i], b[j], acc[i][j]);
        }
        __syncthreads();
    }

#pragma unroll
    for (int i = 0; i < 8; i++) {
        int m = m0 + ty * 8 + i;
        float4 v = make_float4(acc[i][0], acc[i][1], acc[i][2], acc[i][3]);
        *(float4*)&out[(size_t)m * DM + n0 + tx * 4] = v;
    }
}

// ---------------------------------------------------------------------------
// 2D RoPE in-place on g_q / g_k. One thread per rotation pair.
// half 0 (dims 0..31) uses row_ids, half 1 (dims 32..63) uses col_ids.
// Within a half of width 32: pair (i, i+16), ang = pos * 10000^(-i/16).
// gridDim.y: 0 -> q, 1 -> k. Exact coverage (no bounds check).
// ---------------------------------------------------------------------------
__global__ void rope_kernel(const int* __restrict__ row_ids,
                            const int* __restrict__ col_ids) {
    int idx = blockIdx.x * blockDim.x + threadIdx.x;   // < NB*NH*SQ*32
    float* buf = (blockIdx.y == 0) ? g_q : g_k;

    int p    = idx & 31;
    int bhs  = idx >> 5;
    int s    = bhs & (SQ - 1);
    int half = p >> 4;
    int i    = p & 15;

    int pos = (half == 0) ? row_ids[s] : col_ids[s];
    // inv_freq = 10000^(-i/16)
    float inv = expf(-(float)i * (9.210340371976184f / 16.0f));
    float ang = (float)pos * inv;
    float c, sn;
    sincosf(ang, &sn, &c);

    float* v = buf + (size_t)bhs * HD + half * 32;
    float x1 = v[i];
    float x2 = v[i + 16];
    v[i]      = x1 * c - x2 * sn;
    v[i + 16] = x2 * c + x1 * sn;
}

// ---------------------------------------------------------------------------
// Flash attention, fp32. Tile: 64 queries x 64 keys, 256 threads, 4x4/thread.
// Smem operands transposed (stride 68 keeps float4 alignment, spreads banks).
// Online softmax with width-16 shuffle reductions (row group = 16 lanes).
// grid = (S/64 = 32, B*H = 24). Dynamic smem 4*64*68*4 = 69632 B.
// ---------------------------------------------------------------------------
__global__ void attn_kernel() {
    constexpr int STR = 68;
    extern __shared__ __align__(16) float sm[];
    float* Qt = sm;                  // [d][q]
    float* Kt = sm + 64 * STR;       // [d][k]
    float* Vs = sm + 2 * 64 * STR;   // [k][d]
    float* Pt = sm + 3 * 64 * STR;   // [k][q]

    int tid = threadIdx.x;
    int ty = tid >> 4;   // q sub-row (4 rows)
    int tx = tid & 15;   // k / d sub-col (4 cols)
    int bh = blockIdx.y;
    int qt = blockIdx.x;

    const float* Qg = g_q + ((size_t)bh * SQ + qt * 64) * HD;
    const float* Kg = g_k + (size_t)bh * SQ * HD;
    const float* Vg = g_v + (size_t)bh * SQ * HD;

    // load Q tile transposed
#pragma unroll
    for (int i = 0; i < 4; i++) {
        int idx = tid + i * 256;          // 0..1023 float4 slots
        int q   = idx >> 4;               // 0..63
        int d4  = (idx & 15) << 2;        // 0..60
        float4 v = *(const float4*)(Qg + q * HD + d4);
        Qt[(d4 + 0) * STR + q] = v.x; Qt[(d4 + 1) * STR + q] = v.y;
        Qt[(d4 + 2) * STR + q] = v.z; Qt[(d4 + 3) * STR + q] = v.w;
    }

    float m_i[4], l_i[4], o[4][4];
#pragma unroll
    for (int i = 0; i < 4; i++) {
        m_i[i] = -1e30f;
        l_i[i] = 0.0f;
#pragma unroll
        for (int j = 0; j < 4; j++) o[i][j] = 0.0f;
    }

    for (int t = 0; t <= qt; t++) {
        const float* Kgt = Kg + t * 64 * HD;
        const float* Vgt = Vg + t * 64 * HD;
        __syncthreads();   // previous iter's Pt/Vs reads done (also covers Qt on t=0)
#pragma unroll
        for (int i = 0; i < 4; i++) {
            int idx = tid + i * 256;
            int k   = idx >> 4;
            int d4  = (idx & 15) << 2;
            float4 kv = *(const float4*)(Kgt + k * HD + d4);
            Kt[(d4 + 0) * STR + k] = kv.x; Kt[(d4 + 1) * STR + k] = kv.y;
            Kt[(d4 + 2) * STR + k] = kv.z; Kt[(d4 + 3) * STR + k] = kv.w;
            float4 vv = *(const float4*)(Vgt + k * HD + d4);
            *(float4*)&Vs[k * STR + d4] = vv;
        }
        __syncthreads();

        // S = Q K^T
        float s[4][4];
#pragma unroll
        for (int i = 0; i < 4; i++)
#pragma unroll
            for (int j = 0; j < 4; j++) s[i][j] = 0.0f;

#pragma unroll 8
        for (int kk = 0; kk < 64; kk++) {
            float a[4], b[4];
            *(float4*)a = *(const float4*)&Qt[kk * STR + ty * 4];
            *(float4*)b = *(const float4*)&Kt[kk * STR + tx * 4];
#pragma unroll
            for (int i = 0; i < 4; i++)
#pragma unroll
                for (int j = 0; j < 4; j++)
                    s[i][j] = fmaf(a[i], b[j], s[i][j]);
        }

        // scale + causal mask (only the diagonal tile needs masking)
        int qbase = qt * 64 + ty * 4;
        int kbase = t * 64 + tx * 4;
        bool diag = (t == qt);
#pragma unroll
        for (int i = 0; i < 4; i++)
#pragma unroll
            for (int j = 0; j < 4; j++) {
                float sv = s[i][j] * 0.125f;
                if (diag && (kbase + j > qbase + i)) sv = -1e30f;
                s[i][j] = sv;
            }

        // online softmax (row stats across 16 lanes)
#pragma unroll
        for (int i = 0; i < 4; i++) {
            float rm = fmaxf(fmaxf(s[i][0], s[i][1]), fmaxf(s[i][2], s[i][3]));
#pragma unroll
            for (int off = 8; off > 0; off >>= 1)
                rm = fmaxf(rm, __shfl_xor_sync(0xffffffffu, rm, off));
            float mn    = fmaxf(m_i[i], rm);
            float alpha = __expf(m_i[i] - mn);
            m_i[i] = mn;
            float rs = 0.0f;
#pragma unroll
            for (int j = 0; j < 4; j++) {
                float p = __expf(s[i][j] - mn);
                s[i][j] = p;
                rs += p;
            }
#pragma unroll
            for (int off = 8; off > 0; off >>= 1)
                rs += __shfl_xor_sync(0xffffffffu, rs, off);
            l_i[i] = l_i[i] * alpha + rs;
#pragma unroll
            for (int j = 0; j < 4; j++) o[i][j] *= alpha;
        }

        // write P transposed
#pragma unroll
        for (int j = 0; j < 4; j++)
#pragma unroll
            for (int i = 0; i < 4; i++)
                Pt[(tx * 4 + j) * STR + ty * 4 + i] = s[i][j];
        __syncthreads();

        // O += P V
#pragma unroll 8
        for (int kk = 0; kk < 64; kk++) {
            float p[4], vv[4];
            *(float4*)p  = *(const float4*)&Pt[kk * STR + ty * 4];
            *(float4*)vv = *(const float4*)&Vs[kk * STR + tx * 4];
#pragma unroll
            for (int i = 0; i < 4; i++)
#pragma unroll
                for (int j = 0; j < 4; j++)
                    o[i][j] = fmaf(p[i], vv[j], o[i][j]);
        }
    }

    // epilogue: normalize, write (B,S,H*D)
    int b = bh / NH, h = bh % NH;
#pragma unroll
    for (int i = 0; i < 4; i++) {
        float inv = 1.0f / l_i[i];
        int qg = qt * 64 + ty * 4 + i;
        float4 ov = make_float4(o[i][0] * inv, o[i][1] * inv,
                                o[i][2] * inv, o[i][3] * inv);
        *(float4*)&g_attn[((size_t)(b * SQ + qg)) * DM + h * HD + tx * 4] = ov;
    }
}

// ---------------------------------------------------------------------------
extern "C" void kernel_launch(void* const* d_in, const int* in_sizes, int n_in,
                              void* d_out, int out_size) {
    const float* x  = (const float*)d_in[0];
    const int* row  = (const int*)d_in[1];
    const int* col  = (const int*)d_in[2];
    const float* Wq = (const float*)d_in[3];
    const float* Wk = (const float*)d_in[4];
    const float* Wv = (const float*)d_in[5];
    const float* Wo = (const float*)d_in[6];
    float* out = (float*)d_out;

    // 1) QKV projections -> (B,H,S,D)
    qkv_kernel<<<dim3(NH, 32, 3), 256>>>(x, Wq, Wk, Wv);

    // 2) 2D RoPE on q and k
    rope_kernel<<<dim3((NB * NH * SQ * 32) / 256, 2), 256>>>(row, col);

    // 3) flash attention -> (B,S,768)
    cudaFuncSetAttribute(attn_kernel,
                         cudaFuncAttributeMaxDynamicSharedMemorySize,
                         4 * 64 * 68 * 4);
    attn_kernel<<<dim3(SQ / 64, NB * NH), 256, 4 * 64 * 68 * 4>>>();

    // 4) output projection
    outproj_kernel<<<dim3(DM / 64, 32), 256>>>(Wo, out);
}

// round 3
// speedup vs baseline: 3.2956x; 3.2956x over previous
#include <cuda_runtime.h>
#include <cstdint>
#include <math.h>

#define NB 2
#define NH 12
#define SQ 2048
#define HD 64
#define DM 768

// ---------------- scratch (device globals; no allocations allowed) ----------
__device__ float g_q[NB * SQ * DM];          // (B,S,H*D) row-major
__device__ float g_k[NB * SQ * DM];
__device__ float g_v[NB * SQ * DM];
__device__ float g_attn[NB * SQ * DM];

// ============================ helpers =======================================
__device__ __forceinline__ uint32_t smem_u32(const void* p) {
    uint32_t a;
    asm("{ .reg .u64 t; cvta.to.shared.u64 t, %1; cvt.u32.u64 %0, t; }"
        : "=r"(a) : "l"(p));
    return a;
}
__device__ __forceinline__ float to_tf32(float x) {
    float r;
    asm("cvt.rna.tf32.f32 %0, %1;" : "=f"(r) : "f"(x));
    return r;
}
__device__ __forceinline__ void ldsm4(uint32_t* r, uint32_t addr) {
    asm volatile("ldmatrix.sync.aligned.m8n8.x4.shared.b16 {%0,%1,%2,%3}, [%4];"
                 : "=r"(r[0]), "=r"(r[1]), "=r"(r[2]), "=r"(r[3]) : "r"(addr));
}
__device__ __forceinline__ void mma8(float* d, const uint32_t* a,
                                     const uint32_t* b) {
    asm volatile(
        "mma.sync.aligned.m16n8k8.row.col.f32.tf32.tf32.f32 "
        "{%0,%1,%2,%3}, {%4,%5,%6,%7}, {%8,%9}, {%0,%1,%2,%3};"
        : "+f"(d[0]), "+f"(d[1]), "+f"(d[2]), "+f"(d[3])
        : "r"(a[0]), "r"(a[1]), "r"(a[2]), "r"(a[3]), "r"(b[0]), "r"(b[1]));
}

// ============================================================================
// tf32 mma.sync GEMM: C = A(Mx768) @ W(768x768)^T. BM=128 BN=128 BK=32,
// 256 thr (8 warps, 2x4), warp tile 64x32. Reg-prefetch double buffer.
// Smem layout: rows x 8 units of 16B, unit swizz: u = r*8 + (c ^ (r&7)).
// grid (6, M/128, z): z picks (W,C) for fused QKV.
// ============================================================================
#define GEMM_SMEM 65536

__global__ __launch_bounds__(256) void gemm_tc(
    const float* __restrict__ A,
    const float* __restrict__ W0, const float* __restrict__ W1,
    const float* __restrict__ W2,
    float* __restrict__ C0, float* __restrict__ C1, float* __restrict__ C2) {
    const float* W = (blockIdx.z == 0) ? W0 : (blockIdx.z == 1) ? W1 : W2;
    float* C       = (blockIdx.z == 0) ? C0 : (blockIdx.z == 1) ? C1 : C2;

    extern __shared__ __align__(16) float sm[];
    // A bufs: floats [0, 8192), B bufs: [8192, 16384)
    uint32_t smA = smem_u32(sm);          // + buf*16384 bytes
    uint32_t smB = smA + 32768;           // + buf*16384 bytes

    int tid = threadIdx.x, wid = tid >> 5, lane = tid & 31;
    int m0 = blockIdx.y * 128, n0 = blockIdx.x * 128;
    int wm = wid >> 2, wn = wid & 3;

    // ldmatrix fragment addresses
    int t7 = lane & 7;
    int rowA = wm * 64 + t7 + ((lane >> 3) & 1) * 8;
    int cA   = (lane >> 4) & 1;
    int rxA  = rowA & 7;
    int rowB = wn * 32 + t7 + ((lane >> 4) & 1) * 8;
    int cB   = (lane >> 3) & 1;
    int rxB  = rowB & 7;

    // loader indices
    int r_ld = tid >> 3;          // +i*32
    int c_ld = tid & 7;

    const float* Ag = A + (size_t)m0 * DM + c_ld * 4;
    const float* Wg = W + (size_t)n0 * DM + c_ld * 4;

    float acc[4][4][4];
#pragma unroll
    for (int i = 0; i < 4; i++)
#pragma unroll
        for (int j = 0; j < 4; j++)
#pragma unroll
            for (int e = 0; e < 4; e++) acc[i][j][e] = 0.0f;

    float4 ra[4], rb[4];

#define LDG_CHUNK(k0)                                                   \
    do {                                                                \
        _Pragma("unroll") for (int i = 0; i < 4; i++) {                 \
            int r = r_ld + i * 32;                                      \
            ra[i] = *(const float4*)(Ag + (size_t)r * DM + (k0));       \
            rb[i] = *(const float4*)(Wg + (size_t)r * DM + (k0));       \
        }                                                               \
    } while (0)

#define STS_CHUNK(buf)                                                  \
    do {                                                                \
        _Pragma("unroll") for (int i = 0; i < 4; i++) {                 \
            int r = r_ld + i * 32;                                      \
            int u = r * 8 + (c_ld ^ (r & 7));                           \
            float4 va = ra[i];                                          \
            va.x = to_tf32(va.x); va.y = to_tf32(va.y);                 \
            va.z = to_tf32(va.z); va.w = to_tf32(va.w);                 \
            *(float4*)((char*)sm + (buf) * 16384 + u * 16) = va;        \
            float4 vb = rb[i];                                          \
            vb.x = to_tf32(vb.x); vb.y = to_tf32(vb.y);                 \
            vb.z = to_tf32(vb.z); vb.w = to_tf32(vb.w);                 \
            *(float4*)((char*)sm + 32768 + (buf) * 16384 + u * 16) = vb;\
        }                                                               \
    } while (0)

    LDG_CHUNK(0);
    STS_CHUNK(0);
    __syncthreads();

    for (int c = 0; c < DM / 32; c++) {
        int buf = c & 1;
        if (c + 1 < DM / 32) LDG_CHUNK((c + 1) * 32);

        uint32_t Ab = smA + buf * 16384;
        uint32_t Bb = smB + buf * 16384;
#pragma unroll
        for (int ks = 0; ks < 4; ks++) {
            uint32_t af[4][4], bf[2][4];
#pragma unroll
            for (int mt = 0; mt < 4; mt++)
                ldsm4(af[mt], Ab + ((rowA + mt * 16) * 8 +
                                    ((ks * 2 + cA) ^ rxA)) * 16);
#pragma unroll
            for (int np = 0; np < 2; np++)
                ldsm4(bf[np], Bb + ((rowB + np * 16) * 8 +
                                    ((ks * 2 + cB) ^ rxB)) * 16);
#pragma unroll
            for (int mt = 0; mt < 4; mt++)
#pragma unroll
                for (int nt = 0; nt < 4; nt++)
                    mma8(acc[mt][nt], af[mt], &bf[nt >> 1][(nt & 1) * 2]);
        }
        __syncthreads();
        if (c + 1 < DM / 32) {
            STS_CHUNK(1 - buf);
            __syncthreads();
        }
    }

    int g = lane >> 2, tg = lane & 3;
#pragma unroll
    for (int mt = 0; mt < 4; mt++)
#pragma unroll
        for (int nt = 0; nt < 4; nt++)
#pragma unroll
            for (int half = 0; half < 2; half++) {
                int row = m0 + wm * 64 + mt * 16 + g + half * 8;
                int col = n0 + wn * 32 + nt * 8 + tg * 2;
                float2 v = make_float2(acc[mt][nt][half * 2],
                                       acc[mt][nt][half * 2 + 1]);
                *(float2*)&C[(size_t)row * DM + col] = v;
            }
#undef LDG_CHUNK
#undef STS_CHUNK
}

// ---------------------------------------------------------------------------
// 2D RoPE in-place on g_q / g_k, layout (B,S,H,D). One thread per pair.
// ---------------------------------------------------------------------------
__global__ void rope_kernel(const int* __restrict__ row_ids,
                            const int* __restrict__ col_ids) {
    int idx = blockIdx.x * blockDim.x + threadIdx.x;
    float* buf = (blockIdx.y == 0) ? g_q : g_k;

    int p    = idx & 31;
    int bsh  = idx >> 5;
    int s    = (bsh / NH) & (SQ - 1);
    int half = p >> 4;
    int i    = p & 15;

    int pos = (half == 0) ? row_ids[s] : col_ids[s];
    float inv = expf(-(float)i * (9.210340371976184f / 16.0f));
    float ang = (float)pos * inv;
    float c, sn;
    sincosf(ang, &sn, &c);

    float* v = buf + (size_t)bsh * HD + half * 32;
    float x1 = v[i];
    float x2 = v[i + 16];
    v[i]      = x1 * c - x2 * sn;
    v[i + 16] = x2 * c + x1 * sn;
}

// ============================================================================
// Flash attention on mma.sync tf32. CTA: 128 q rows x 64 k cols per iter,
// 256 thr (8 warps), each warp owns 16 q rows. Q/K/P smem swizzled for
// ldmatrix; V transposed into smem so PV B-operand also uses ldmatrix.
// grid: 1D 384, heavy (large qt) first for causal balance.
// ============================================================================
#define ATT_SMEM 98304

__global__ __launch_bounds__(256) void attn_tc() {
    extern __shared__ __align__(16) float sm[];
    float* Qs = sm;             // 128 rows x 16 units (8192 f)
    float* Ks = sm + 8192;      // 64 x 16 (4096 f)
    float* Vt = sm + 12288;     // 64(d) x 16 (4096 f), transposed V
    float* Ps = sm + 16384;     // 128 x 16 (8192 f)

    int tid = threadIdx.x, wid = tid >> 5, lane = tid & 31;
    int bx = blockIdx.x;
    int qt = (SQ / 128 - 1) - bx / (NB * NH);
    int bh = bx % (NB * NH);
    int b = bh / NH, h = bh % NH;

    const float* Qg = g_q + ((size_t)(b * SQ + qt * 128)) * DM + h * HD;
    const float* Kg = g_k + (size_t)b * SQ * DM + h * HD;
    const float* Vg = g_v + (size_t)b * SQ * DM + h * HD;

    // load Q (128x64), swizzled, tf32
#pragma unroll
    for (int i = 0; i < 8; i++) {
        int idx = tid + i * 256;
        int r = idx >> 4, c16 = idx & 15;
        float4 v = *(const float4*)(Qg + (size_t)r * DM + c16 * 4);
        v.x = to_tf32(v.x); v.y = to_tf32(v.y);
        v.z = to_tf32(v.z); v.w = to_tf32(v.w);
        *(float4*)&Qs[(r * 16 + (c16 ^ (r & 7))) * 4] = v;
    }

    int t7 = lane & 7, g = lane >> 2, tg = lane & 3;
    int rowA = wid * 16 + t7 + ((lane >> 3) & 1) * 8;
    int cA   = (lane >> 4) & 1;
    int rxA  = rowA & 7;
    int rowB = t7 + ((lane >> 4) & 1) * 8;   // + np*16
    int cB   = (lane >> 3) & 1;
    int rxB  = rowB & 7;

    uint32_t Qb = smem_u32(Qs), Kb = smem_u32(Ks);
    uint32_t Vb = smem_u32(Vt), Pb = smem_u32(Ps);

    // P-store address pieces
    int prow = wid * 16 + g;
    int prx  = prow & 7;

    float o[8][4];
#pragma unroll
    for (int i = 0; i < 8; i++)
#pragma unroll
        for (int e = 0; e < 4; e++) o[i][e] = 0.0f;
    float m0r = -1e30f, m1r = -1e30f, l0 = 0.0f, l1 = 0.0f;

    int qwarp = qt * 128 + wid * 16;
    int nkt = 2 * qt + 2;

    for (int t = 0; t < nkt; t++) {
        int k0 = t * 64;
        __syncthreads();   // everyone done reading Ks/Vt/Ps from prev iter
        // load K and V(transposed), tf32
#pragma unroll
        for (int i = 0; i < 4; i++) {
            int idx = tid + i * 256;
            int r = idx >> 4, c16 = idx & 15;
            float4 kv = *(const float4*)(Kg + (size_t)(k0 + r) * DM + c16 * 4);
            kv.x = to_tf32(kv.x); kv.y = to_tf32(kv.y);
            kv.z = to_tf32(kv.z); kv.w = to_tf32(kv.w);
            *(float4*)&Ks[(r * 16 + (c16 ^ (r & 7))) * 4] = kv;
            float4 vv = *(const float4*)(Vg + (size_t)(k0 + r) * DM + c16 * 4);
            float vj[4] = {to_tf32(vv.x), to_tf32(vv.y),
                           to_tf32(vv.z), to_tf32(vv.w)};
#pragma unroll
            for (int j = 0; j < 4; j++) {
                int d = c16 * 4 + j;
                Vt[(d * 16 + ((r >> 2) ^ (d & 7))) * 4 + (r & 3)] = vj[j];
            }
        }
        __syncthreads();

        bool active = (k0 <= qwarp + 15);
        if (active) {
            float s[8][4];
#pragma unroll
            for (int i = 0; i < 8; i++)
#pragma unroll
                for (int e = 0; e < 4; e++) s[i][e] = 0.0f;

#pragma unroll
            for (int ks = 0; ks < 8; ks++) {
                uint32_t aq[4], bk[4][4];
                ldsm4(aq, Qb + (rowA * 16 + ((ks * 2 + cA) ^ rxA)) * 16);
#pragma unroll
                for (int np = 0; np < 4; np++)
                    ldsm4(bk[np], Kb + ((rowB + np * 16) * 16 +
                                        ((ks * 2 + cB) ^ rxB)) * 16);
#pragma unroll
                for (int nt = 0; nt < 8; nt++)
                    mma8(s[nt], aq, &bk[nt >> 1][(nt & 1) * 2]);
            }

            // scale + causal mask
            if (k0 + 63 > qwarp) {
#pragma unroll
                for (int nt = 0; nt < 8; nt++)
#pragma unroll
                    for (int e = 0; e < 4; e++) {
                        int colg = k0 + nt * 8 + tg * 2 + (e & 1);
                        int rowg = qwarp + g + (e >> 1) * 8;
                        float v = s[nt][e] * 0.125f;
                        s[nt][e] = (colg > rowg) ? -1e30f : v;
                    }
            } else {
#pragma unroll
                for (int nt = 0; nt < 8; nt++)
#pragma unroll
                    for (int e = 0; e < 4; e++) s[nt][e] *= 0.125f;
            }

            // online softmax
            float rm0 = -1e30f, rm1 = -1e30f;
#pragma unroll
            for (int nt = 0; nt < 8; nt++) {
                rm0 = fmaxf(rm0, fmaxf(s[nt][0], s[nt][1]));
                rm1 = fmaxf(rm1, fmaxf(s[nt][2], s[nt][3]));
            }
            rm0 = fmaxf(rm0, __shfl_xor_sync(0xffffffffu, rm0, 1));
            rm0 = fmaxf(rm0, __shfl_xor_sync(0xffffffffu, rm0, 2));
            rm1 = fmaxf(rm1, __shfl_xor_sync(0xffffffffu, rm1, 1));
            rm1 = fmaxf(rm1, __shfl_xor_sync(0xffffffffu, rm1, 2));
            float mn0 = fmaxf(m0r, rm0), mn1 = fmaxf(m1r, rm1);
            float al0 = __expf(m0r - mn0), al1 = __expf(m1r - mn1);
            m0r = mn0; m1r = mn1;
            float rs0 = 0.0f, rs1 = 0.0f;
#pragma unroll
            for (int nt = 0; nt < 8; nt++) {
                float p0 = __expf(s[nt][0] - mn0);
                float p1 = __expf(s[nt][1] - mn0);
                float p2 = __expf(s[nt][2] - mn1);
                float p3 = __expf(s[nt][3] - mn1);
                rs0 += p0 + p1;
                rs1 += p2 + p3;
                int c16 = nt * 2 + (tg >> 1);
                int boff = (tg & 1) * 8;
                float2 v0 = make_float2(to_tf32(p0), to_tf32(p1));
                *(float2*)((char*)Ps + (prow * 16 + (c16 ^ prx)) * 16 + boff) = v0;
                float2 v1 = make_float2(to_tf32(p2), to_tf32(p3));
                *(float2*)((char*)Ps + ((prow + 8) * 16 + (c16 ^ prx)) * 16 +
                           boff) = v1;
            }
            l0 = l0 * al0 + rs0;
            l1 = l1 * al1 + rs1;
#pragma unroll
            for (int nt = 0; nt < 8; nt++) {
                o[nt][0] *= al0; o[nt][1] *= al0;
                o[nt][2] *= al1; o[nt][3] *= al1;
            }
        }
        __syncthreads();   // P_s/Vt visible to warp's own ldmatrix (per-warp ok)
        if (active) {
#pragma unroll
            for (int ks = 0; ks < 8; ks++) {
                uint32_t ap[4], bv[4][4];
                ldsm4(ap, Pb + (rowA * 16 + ((ks * 2 + cA) ^ rxA)) * 16);
#pragma unroll
                for (int np = 0; np < 4; np++)
                    ldsm4(bv[np], Vb + ((rowB + np * 16) * 16 +
                                        ((ks * 2 + cB) ^ rxB)) * 16);
#pragma unroll
                for (int nt = 0; nt < 8; nt++)
                    mma8(o[nt], ap, &bv[nt >> 1][(nt & 1) * 2]);
            }
        }
    }

    // final: reduce l across the 4 lanes of each row, normalize, store
    l0 += __shfl_xor_sync(0xffffffffu, l0, 1);
    l0 += __shfl_xor_sync(0xffffffffu, l0, 2);
    l1 += __shfl_xor_sync(0xffffffffu, l1, 1);
    l1 += __shfl_xor_sync(0xffffffffu, l1, 2);
    float inv0 = 1.0f / l0, inv1 = 1.0f / l1;

    float* Og = g_attn + ((size_t)(b * SQ + qt * 128 + wid * 16)) * DM + h * HD;
#pragma unroll
    for (int nt = 0; nt < 8; nt++) {
        int col = nt * 8 + tg * 2;
        float2 v0 = make_float2(o[nt][0] * inv0, o[nt][1] * inv0);
        *(float2*)&Og[(size_t)g * DM + col] = v0;
        float2 v1 = make_float2(o[nt][2] * inv1, o[nt][3] * inv1);
        *(float2*)&Og[(size_t)(g + 8) * DM + col] = v1;
    }
}

// ---------------------------------------------------------------------------
extern "C" void kernel_launch(void* const* d_in, const int* in_sizes, int n_in,
                              void* d_out, int out_size) {
    const float* x  = (const float*)d_in[0];
    const int* row  = (const int*)d_in[1];
    const int* col  = (const int*)d_in[2];
    const float* Wq = (const float*)d_in[3];
    const float* Wk = (const float*)d_in[4];
    const float* Wv = (const float*)d_in[5];
    const float* Wo = (const float*)d_in[6];
    float* out = (float*)d_out;

    void *qp, *kp, *vp, *ap;
    cudaGetSymbolAddress(&qp, g_q);
    cudaGetSymbolAddress(&kp, g_k);
    cudaGetSymbolAddress(&vp, g_v);
    cudaGetSymbolAddress(&ap, g_attn);

    cudaFuncSetAttribute(gemm_tc, cudaFuncAttributeMaxDynamicSharedMemorySize,
                         GEMM_SMEM);
    cudaFuncSetAttribute(attn_tc, cudaFuncAttributeMaxDynamicSharedMemorySize,
                         ATT_SMEM);

    // 1) fused QKV projections (tf32 mma.sync) -> (B,S,H*D)
    gemm_tc<<<dim3(DM / 128, (NB * SQ) / 128, 3), 256, GEMM_SMEM>>>(
        x, Wq, Wk, Wv, (float*)qp, (float*)kp, (float*)vp);

    // 2) 2D RoPE on q and k
    rope_kernel<<<dim3((NB * SQ * NH * 32) / 256, 2), 256>>>(row, col);

    // 3) flash attention (tf32 mma.sync) -> (B,S,768)
    attn_tc<<<(SQ / 128) * NB * NH, 256, ATT_SMEM>>>();

    // 4) output projection
    gemm_tc<<<dim3(DM / 128, (NB * SQ) / 128, 1), 256, GEMM_SMEM>>>(
        (const float*)ap, Wo, Wo, Wo, out, out, out);
}

// round 4
// speedup vs baseline: 3.9374x; 1.1947x over previous
#include <cuda_runtime.h>
#include <cstdint>
#include <math.h>

#define NB 2
#define NH 12
#define SQ 2048
#define HD 64
#define DM 768
#define NCH (DM / 32)   // 24 k-chunks

// ---------------- scratch (device globals; no allocations allowed) ----------
__device__ float g_q[NB * SQ * DM];          // (B,S,H*D) tf32 after rope
__device__ float g_k[NB * SQ * DM];
__device__ float g_v[NB * SQ * DM];          // fp32 from gemm
__device__ float g_vt[NB * NH * HD * SQ];    // (bh, d, s) tf32
__device__ float g_attn[NB * SQ * DM];       // tf32 (attn out)
__device__ float g_x[NB * SQ * DM];          // tf32 x
__device__ float g_wq[DM * DM], g_wk[DM * DM], g_wv[DM * DM], g_wo[DM * DM];

// ============================ helpers =======================================
__device__ __forceinline__ uint32_t smem_u32(const void* p) {
    uint32_t a;
    asm("{ .reg .u64 t; cvta.to.shared.u64 t, %1; cvt.u32.u64 %0, t; }"
        : "=r"(a) : "l"(p));
    return a;
}
__device__ __forceinline__ float to_tf32(float x) {
    float r;
    asm("cvt.rna.tf32.f32 %0, %1;" : "=f"(r) : "f"(x));
    return r;
}
__device__ __forceinline__ void ldsm4(uint32_t* r, uint32_t addr) {
    asm volatile("ldmatrix.sync.aligned.m8n8.x4.shared.b16 {%0,%1,%2,%3}, [%4];"
                 : "=r"(r[0]), "=r"(r[1]), "=r"(r[2]), "=r"(r[3]) : "r"(addr));
}
__device__ __forceinline__ void mma8(float* d, const uint32_t* a,
                                     const uint32_t* b) {
    asm volatile(
        "mma.sync.aligned.m16n8k8.row.col.f32.tf32.tf32.f32 "
        "{%0,%1,%2,%3}, {%4,%5,%6,%7}, {%8,%9}, {%0,%1,%2,%3};"
        : "+f"(d[0]), "+f"(d[1]), "+f"(d[2]), "+f"(d[3])
        : "r"(a[0]), "r"(a[1]), "r"(a[2]), "r"(a[3]), "r"(b[0]), "r"(b[1]));
}
__device__ __forceinline__ void cp16(uint32_t dst, const void* src) {
    asm volatile("cp.async.cg.shared.global [%0], [%1], 16;"
                 :: "r"(dst), "l"(src));
}
#define CP_COMMIT() asm volatile("cp.async.commit_group;" ::: "memory")
#define CP_WAIT(n)  asm volatile("cp.async.wait_group " #n ";" ::: "memory")

// ============================================================================
// tf32 cvt prep kernel (float4 granularity)
// ============================================================================
__global__ void cvt_kernel(const float4* __restrict__ src,
                           float4* __restrict__ dst, int n4) {
    int i = blockIdx.x * 256 + threadIdx.x;
    if (i < n4) {
        float4 v = src[i];
        v.x = to_tf32(v.x); v.y = to_tf32(v.y);
        v.z = to_tf32(v.z); v.w = to_tf32(v.w);
        dst[i] = v;
    }
}

// ============================================================================
// GEMM: C = A(MxDM) @ W(DMxDM)^T. Inputs pre-tf32. BM x 128 tiles, BK=32,
// 256 thr (8 warps 2x4), 3-stage cp.async pipeline, 1 barrier per chunk.
// ============================================================================
template <int BM>
__global__ __launch_bounds__(256, 2) void gemm_tc(
    const float* __restrict__ A,
    const float* __restrict__ W0, const float* __restrict__ W1,
    const float* __restrict__ W2,
    float* __restrict__ C0, float* __restrict__ C1, float* __restrict__ C2) {
    const float* W = (blockIdx.z == 0) ? W0 : (blockIdx.z == 1) ? W1 : W2;
    float* C       = (blockIdx.z == 0) ? C0 : (blockIdx.z == 1) ? C1 : C2;

    constexpr int MT = BM / 32;            // warp m-tiles (16 rows each)
    constexpr int ABYTES = BM * 32 * 4;    // per-stage A bytes

    extern __shared__ __align__(16) float sm[];
    uint32_t smA = smem_u32(sm);
    uint32_t smB = smA + 3 * ABYTES;

    int tid = threadIdx.x, wid = tid >> 5, lane = tid & 31;
    int m0 = blockIdx.y * BM, n0 = blockIdx.x * 128;
    int wm = wid >> 2, wn = wid & 3;

    int t7 = lane & 7;
    int rowA = wm * (BM / 2) + t7 + ((lane >> 3) & 1) * 8;
    int cA   = (lane >> 4) & 1;
    int rxA  = rowA & 7;
    int rowB = wn * 32 + t7 + ((lane >> 4) & 1) * 8;
    int cB   = (lane >> 3) & 1;
    int rxB  = rowB & 7;

    const float* Ag = A + (size_t)m0 * DM;
    const float* Wg = W + (size_t)n0 * DM;

#define G_ISSUE(c)                                                          \
    do {                                                                    \
        int _buf = (c) % 3;                                                 \
        uint32_t _sa = smA + _buf * ABYTES;                                 \
        uint32_t _sb = smB + _buf * 16384;                                  \
        _Pragma("unroll") for (int i = 0; i < BM / 32; i++) {               \
            int idx = tid + i * 256;                                        \
            int r = idx >> 3, u = idx & 7;                                  \
            cp16(_sa + (r * 8 + (u ^ (r & 7))) * 16,                        \
                 Ag + (size_t)r * DM + (c) * 32 + u * 4);                   \
        }                                                                   \
        _Pragma("unroll") for (int i = 0; i < 4; i++) {                     \
            int idx = tid + i * 256;                                        \
            int r = idx >> 3, u = idx & 7;                                  \
            cp16(_sb + (r * 8 + (u ^ (r & 7))) * 16,                        \
                 Wg + (size_t)r * DM + (c) * 32 + u * 4);                   \
        }                                                                   \
    } while (0)

    G_ISSUE(0); CP_COMMIT();
    G_ISSUE(1); CP_COMMIT();

    float acc[MT][4][4];
#pragma unroll
    for (int i = 0; i < MT; i++)
#pragma unroll
        for (int j = 0; j < 4; j++)
#pragma unroll
            for (int e = 0; e < 4; e++) acc[i][j][e] = 0.0f;

    for (int c = 0; c < NCH; c++) {
        CP_WAIT(1);
        __syncthreads();
        if (c + 2 < NCH) G_ISSUE(c + 2);
        CP_COMMIT();

        int buf = c % 3;
        uint32_t Ab = smA + buf * ABYTES;
        uint32_t Bb = smB + buf * 16384;
#pragma unroll
        for (int ks = 0; ks < 4; ks++) {
            uint32_t af[MT][4], bf[2][4];
#pragma unroll
            for (int mt = 0; mt < MT; mt++)
                ldsm4(af[mt], Ab + ((rowA + mt * 16) * 8 +
                                    ((ks * 2 + cA) ^ rxA)) * 16);
#pragma unroll
            for (int np = 0; np < 2; np++)
                ldsm4(bf[np], Bb + ((rowB + np * 16) * 8 +
                                    ((ks * 2 + cB) ^ rxB)) * 16);
#pragma unroll
            for (int mt = 0; mt < MT; mt++)
#pragma unroll
                for (int nt = 0; nt < 4; nt++)
                    mma8(acc[mt][nt], af[mt], &bf[nt >> 1][(nt & 1) * 2]);
        }
    }

    int g = lane >> 2, tg = lane & 3;
#pragma unroll
    for (int mt = 0; mt < MT; mt++)
#pragma unroll
        for (int nt = 0; nt < 4; nt++)
#pragma unroll
            for (int half = 0; half < 2; half++) {
                int row = m0 + wm * (BM / 2) + mt * 16 + g + half * 8;
                int col = n0 + wn * 32 + nt * 8 + tg * 2;
                float2 v = make_float2(acc[mt][nt][half * 2],
                                       acc[mt][nt][half * 2 + 1]);
                *(float2*)&C[(size_t)row * DM + col] = v;
            }
#undef G_ISSUE
}

// ---------------------------------------------------------------------------
// 2D RoPE in-place on g_q / g_k, writes tf32-rounded.
// ---------------------------------------------------------------------------
__global__ void rope_kernel(const int* __restrict__ row_ids,
                            const int* __restrict__ col_ids) {
    int idx = blockIdx.x * blockDim.x + threadIdx.x;
    float* buf = (blockIdx.y == 0) ? g_q : g_k;

    int p    = idx & 31;
    int bsh  = idx >> 5;
    int s    = (bsh / NH) & (SQ - 1);
    int half = p >> 4;
    int i    = p & 15;

    int pos = (half == 0) ? row_ids[s] : col_ids[s];
    float inv = expf(-(float)i * (9.210340371976184f / 16.0f));
    float ang = (float)pos * inv;
    float c, sn;
    sincosf(ang, &sn, &c);

    float* v = buf + (size_t)bsh * HD + half * 32;
    float x1 = v[i];
    float x2 = v[i + 16];
    v[i]      = to_tf32(x1 * c - x2 * sn);
    v[i + 16] = to_tf32(x2 * c + x1 * sn);
}

// ---------------------------------------------------------------------------
// V transpose: g_v (b,s,h*64+d) fp32 -> g_vt (b*NH+h, d, s) tf32.
// Blocks 32x8, 32x32 tiles. grid (SQ/32, HD/32, NB*NH).
// ---------------------------------------------------------------------------
__global__ void vtrans_kernel() {
    __shared__ float t[32][33];
    int bh = blockIdx.z;
    int b = bh / NH, h = bh % NH;
    int s0 = blockIdx.x * 32, d0 = blockIdx.y * 32;
    int tx = threadIdx.x, ty = threadIdx.y;

    const float* src = g_v + (size_t)b * SQ * DM + h * HD;
#pragma unroll
    for (int k = 0; k < 4; k++)
        t[ty + k * 8][tx] = src[(size_t)(s0 + ty + k * 8) * DM + d0 + tx];
    __syncthreads();
    float* dst = g_vt + ((size_t)bh * HD + d0) * SQ + s0;
#pragma unroll
    for (int k = 0; k < 4; k++)
        dst[(size_t)(ty + k * 8) * SQ + tx] = to_tf32(t[tx][ty + k * 8]);
}

// ============================================================================
// Flash attention, tf32 mma.sync, cp.async double-buffered K/Vt, P repacked
// in registers via shuffles (no P smem). CTA: 128q x 64k, 8 warps.
// smem: Q 32KB + K 2x16KB + Vt 2x16KB = 96KB -> 2 CTA/SM.
// ============================================================================
#define ATT_SMEM 98304

__global__ __launch_bounds__(256, 2) void attn_tc() {
    extern __shared__ __align__(16) float sm[];
    uint32_t Qb    = smem_u32(sm);
    uint32_t Kbase = Qb + 32768;
    uint32_t Vbase = Qb + 65536;

    int tid = threadIdx.x, wid = tid >> 5, lane = tid & 31;
    int bx = blockIdx.x;
    int qt = (SQ / 128 - 1) - bx / (NB * NH);
    int bh = bx % (NB * NH);
    int b = bh / NH, h = bh % NH;

    const float* Qg  = g_q + ((size_t)(b * SQ + qt * 128)) * DM + h * HD;
    const float* Kg  = g_k + (size_t)b * SQ * DM + h * HD;
    const float* Vtg = g_vt + (size_t)bh * HD * SQ;

    int nkt = 2 * qt + 2;

    // prologue: issue K/V tile 0
#define KV_ISSUE(t)                                                         \
    do {                                                                    \
        if ((t) < nkt) {                                                    \
            int _k0 = (t) * 64;                                             \
            uint32_t _ks = Kbase + ((t) & 1) * 16384;                       \
            uint32_t _vs = Vbase + ((t) & 1) * 16384;                       \
            _Pragma("unroll") for (int i = 0; i < 4; i++) {                 \
                int idx = tid + i * 256;                                    \
                int r = idx >> 4, u = idx & 15;                             \
                cp16(_ks + (r * 16 + (u ^ (r & 7))) * 16,                   \
                     Kg + (size_t)(_k0 + r) * DM + u * 4);                  \
                cp16(_vs + (r * 16 + (u ^ (r & 7))) * 16,                   \
                     Vtg + (size_t)r * SQ + _k0 + u * 4);                   \
            }                                                               \
        }                                                                   \
    } while (0)

    KV_ISSUE(0); CP_COMMIT();

    // load Q (128x64), scaled by 1/8 (exact in tf32), swizzled
#pragma unroll
    for (int i = 0; i < 8; i++) {
        int idx = tid + i * 256;
        int r = idx >> 4, u = idx & 15;
        float4 v = *(const float4*)(Qg + (size_t)r * DM + u * 4);
        v.x *= 0.125f; v.y *= 0.125f; v.z *= 0.125f; v.w *= 0.125f;
        *(float4*)&sm[(r * 16 + (u ^ (r & 7))) * 4] = v;
    }

    int t7 = lane & 7, g = lane >> 2, tg = lane & 3;
    int rowA = wid * 16 + t7 + ((lane >> 3) & 1) * 8;
    int cA   = (lane >> 4) & 1;
    int rxA  = rowA & 7;
    int rowB = t7 + ((lane >> 4) & 1) * 8;
    int cB   = (lane >> 3) & 1;
    int rxB  = rowB & 7;

    int src0 = (lane & 28) | (tg >> 1);
    int src1 = src0 + 2;
    bool oddc = tg & 1;

    float o[8][4];
#pragma unroll
    for (int i = 0; i < 8; i++)
#pragma unroll
        for (int e = 0; e < 4; e++) o[i][e] = 0.0f;
    float m0r = -1e30f, m1r = -1e30f, l0 = 0.0f, l1 = 0.0f;

    int qwarp = qt * 128 + wid * 16;

    for (int t = 0; t < nkt; t++) {
        int k0 = t * 64;
        CP_WAIT(0);
        __syncthreads();          // tile t ready; all warps done with buf t&1^1
        KV_ISSUE(t + 1); CP_COMMIT();

        uint32_t Kb = Kbase + (t & 1) * 16384;
        uint32_t Vb = Vbase + (t & 1) * 16384;

        bool active = (k0 <= qwarp + 15);
        if (active) {
            float s[8][4];
#pragma unroll
            for (int i = 0; i < 8; i++)
#pragma unroll
                for (int e = 0; e < 4; e++) s[i][e] = 0.0f;

#pragma unroll
            for (int ks = 0; ks < 8; ks++) {
                uint32_t aq[4], bk[4][4];
                ldsm4(aq, Qb + (rowA * 16 + ((ks * 2 + cA) ^ rxA)) * 16);
#pragma unroll
                for (int np = 0; np < 4; np++)
                    ldsm4(bk[np], Kb + ((rowB + np * 16) * 16 +
                                        ((ks * 2 + cB) ^ rxB)) * 16);
#pragma unroll
                for (int nt = 0; nt < 8; nt++)
                    mma8(s[nt], aq, &bk[nt >> 1][(nt & 1) * 2]);
            }

            // causal mask (only boundary tiles)
            if (k0 + 63 > qwarp) {
#pragma unroll
                for (int nt = 0; nt < 8; nt++)
#pragma unroll
                    for (int e = 0; e < 4; e++) {
                        int colg = k0 + nt * 8 + tg * 2 + (e & 1);
                        int rowg = qwarp + g + (e >> 1) * 8;
                        if (colg > rowg) s[nt][e] = -1e30f;
                    }
            }

            // online softmax (rows g and g+8)
            float rm0 = -1e30f, rm1 = -1e30f;
#pragma unroll
            for (int nt = 0; nt < 8; nt++) {
                rm0 = fmaxf(rm0, fmaxf(s[nt][0], s[nt][1]));
                rm1 = fmaxf(rm1, fmaxf(s[nt][2], s[nt][3]));
            }
            rm0 = fmaxf(rm0, __shfl_xor_sync(0xffffffffu, rm0, 1));
            rm0 = fmaxf(rm0, __shfl_xor_sync(0xffffffffu, rm0, 2));
            rm1 = fmaxf(rm1, __shfl_xor_sync(0xffffffffu, rm1, 1));
            rm1 = fmaxf(rm1, __shfl_xor_sync(0xffffffffu, rm1, 2));
            float mn0 = fmaxf(m0r, rm0), mn1 = fmaxf(m1r, rm1);
            float al0 = __expf(m0r - mn0), al1 = __expf(m1r - mn1);
            m0r = mn0; m1r = mn1;
            float rs0 = 0.0f, rs1 = 0.0f;
#pragma unroll
            for (int nt = 0; nt < 8; nt++) {
                float p0 = __expf(s[nt][0] - mn0);
                float p1 = __expf(s[nt][1] - mn0);
                float p2 = __expf(s[nt][2] - mn1);
                float p3 = __expf(s[nt][3] - mn1);
                rs0 += p0 + p1;
                rs1 += p2 + p3;
                s[nt][0] = to_tf32(p0); s[nt][1] = to_tf32(p1);
                s[nt][2] = to_tf32(p2); s[nt][3] = to_tf32(p3);
            }
            l0 = l0 * al0 + rs0;
            l1 = l1 * al1 + rs1;
#pragma unroll
            for (int nt = 0; nt < 8; nt++) {
                o[nt][0] *= al0; o[nt][1] *= al0;
                o[nt][2] *= al1; o[nt][3] *= al1;
            }

            // PV: repack P C-frag -> A-frag via shuffles, mma against Vt
#pragma unroll
            for (int kb = 0; kb < 8; kb++) {
                float v00 = __shfl_sync(0xffffffffu, s[kb][0], src0);
                float v01 = __shfl_sync(0xffffffffu, s[kb][1], src0);
                float v10 = __shfl_sync(0xffffffffu, s[kb][2], src0);
                float v11 = __shfl_sync(0xffffffffu, s[kb][3], src0);
                float w00 = __shfl_sync(0xffffffffu, s[kb][0], src1);
                float w01 = __shfl_sync(0xffffffffu, s[kb][1], src1);
                float w10 = __shfl_sync(0xffffffffu, s[kb][2], src1);
                float w11 = __shfl_sync(0xffffffffu, s[kb][3], src1);
                uint32_t ap[4];
                ap[0] = __float_as_uint(oddc ? v01 : v00);   // P[g][tg]
                ap[1] = __float_as_uint(oddc ? v11 : v10);   // P[g+8][tg]
                ap[2] = __float_as_uint(oddc ? w01 : w00);   // P[g][tg+4]
                ap[3] = __float_as_uint(oddc ? w11 : w10);   // P[g+8][tg+4]
                uint32_t bv[4][4];
#pragma unroll
                for (int np = 0; np < 4; np++)
                    ldsm4(bv[np], Vb + ((rowB + np * 16) * 16 +
                                        ((kb * 2 + cB) ^ rxB)) * 16);
#pragma unroll
                for (int nt = 0; nt < 8; nt++)
                    mma8(o[nt], ap, &bv[nt >> 1][(nt & 1) * 2]);
            }
        }
    }

    // final: reduce l, normalize, store tf32 to g_attn
    l0 += __shfl_xor_sync(0xffffffffu, l0, 1);
    l0 += __shfl_xor_sync(0xffffffffu, l0, 2);
    l1 += __shfl_xor_sync(0xffffffffu, l1, 1);
    l1 += __shfl_xor_sync(0xffffffffu, l1, 2);
    float inv0 = 1.0f / l0, inv1 = 1.0f / l1;

    float* Og = g_attn + ((size_t)(b * SQ + qt * 128 + wid * 16)) * DM + h * HD;
#pragma unroll
    for (int nt = 0; nt < 8; nt++) {
        int col = nt * 8 + tg * 2;
        float2 v0 = make_float2(to_tf32(o[nt][0] * inv0),
                                to_tf32(o[nt][1] * inv0));
        *(float2*)&Og[(size_t)g * DM + col] = v0;
        float2 v1 = make_float2(to_tf32(o[nt][2] * inv1),
                                to_tf32(o[nt][3] * inv1));
        *(float2*)&Og[(size_t)(g + 8) * DM + col] = v1;
    }
#undef KV_ISSUE
}

// ---------------------------------------------------------------------------
extern "C" void kernel_launch(void* const* d_in, const int* in_sizes, int n_in,
                              void* d_out, int out_size) {
    const float* x  = (const float*)d_in[0];
    const int* row  = (const int*)d_in[1];
    const int* col  = (const int*)d_in[2];
    const float* Wq = (const float*)d_in[3];
    const float* Wk = (const float*)d_in[4];
    const float* Wv = (const float*)d_in[5];
    const float* Wo = (const float*)d_in[6];
    float* out = (float*)d_out;

    void *qp, *kp, *vp, *ap, *xp, *wqp, *wkp, *wvp, *wop;
    cudaGetSymbolAddress(&qp, g_q);
    cudaGetSymbolAddress(&kp, g_k);
    cudaGetSymbolAddress(&vp, g_v);
    cudaGetSymbolAddress(&ap, g_attn);
    cudaGetSymbolAddress(&xp, g_x);
    cudaGetSymbolAddress(&wqp, g_wq);
    cudaGetSymbolAddress(&wkp, g_wk);
    cudaGetSymbolAddress(&wvp, g_wv);
    cudaGetSymbolAddress(&wop, g_wo);

    cudaFuncSetAttribute(gemm_tc<128>,
                         cudaFuncAttributeMaxDynamicSharedMemorySize, 98304);
    cudaFuncSetAttribute(gemm_tc<64>,
                         cudaFuncAttributeMaxDynamicSharedMemorySize, 73728);
    cudaFuncSetAttribute(attn_tc,
                         cudaFuncAttributeMaxDynamicSharedMemorySize, ATT_SMEM);

    // 0) tf32 pre-conversion of x and weights
    int n4x = NB * SQ * DM / 4, n4w = DM * DM / 4;
    cvt_kernel<<<(n4x + 255) / 256, 256>>>((const float4*)x, (float4*)xp, n4x);
    cvt_kernel<<<(n4w + 255) / 256, 256>>>((const float4*)Wq, (float4*)wqp, n4w);
    cvt_kernel<<<(n4w + 255) / 256, 256>>>((const float4*)Wk, (float4*)wkp, n4w);
    cvt_kernel<<<(n4w + 255) / 256, 256>>>((const float4*)Wv, (float4*)wvp, n4w);
    cvt_kernel<<<(n4w + 255) / 256, 256>>>((const float4*)Wo, (float4*)wop, n4w);

    // 1) fused QKV projections
    gemm_tc<128><<<dim3(DM / 128, (NB * SQ) / 128, 3), 256, 98304>>>(
        (const float*)xp, (const float*)wqp, (const float*)wkp,
        (const float*)wvp, (float*)qp, (float*)kp, (float*)vp);

    // 2) 2D RoPE (q,k -> tf32) + V transpose (-> tf32)
    rope_kernel<<<dim3((NB * SQ * NH * 32) / 256, 2), 256>>>(row, col);
    vtrans_kernel<<<dim3(SQ / 32, HD / 32, NB * NH), dim3(32, 8)>>>();

    // 3) flash attention
    attn_tc<<<(SQ / 128) * NB * NH, 256, ATT_SMEM>>>();

    // 4) output projection (BM=64 for grid balance)
    gemm_tc<64><<<dim3(DM / 128, (NB * SQ) / 64, 1), 256, 73728>>>(
        (const float*)ap, (const float*)wop, (const float*)wop,
        (const float*)wop, out, out, out);
}

// round 5
// speedup vs baseline: 4.4521x; 1.1307x over previous
#include <cuda_runtime.h>
#include <cstdint>
#include <math.h>

#define NB 2
#define NH 12
#define SQ 2048
#define HD 64
#define DM 768
#define NCH (DM / 32)   // 24 k-chunks

// ---------------- scratch (device globals; no allocations allowed) ----------
__device__ float g_q[NB * SQ * DM];          // (B,S,H*D) tf32 after rope
__device__ float g_k[NB * SQ * DM];
__device__ float g_vt[NB * NH * HD * SQ];    // (bh, d, s) tf32
__device__ float g_attn[NB * SQ * DM];       // tf32 (attn out)
__device__ float g_x[NB * SQ * DM];          // tf32 x
__device__ float g_wq[DM * DM], g_wk[DM * DM], g_wv[DM * DM], g_wo[DM * DM];

// ============================ helpers =======================================
__device__ __forceinline__ uint32_t smem_u32(const void* p) {
    uint32_t a;
    asm("{ .reg .u64 t; cvta.to.shared.u64 t, %1; cvt.u32.u64 %0, t; }"
        : "=r"(a) : "l"(p));
    return a;
}
__device__ __forceinline__ float to_tf32(float x) {
    float r;
    asm("cvt.rna.tf32.f32 %0, %1;" : "=f"(r) : "f"(x));
    return r;
}
__device__ __forceinline__ void ldsm4(uint32_t* r, uint32_t addr) {
    asm volatile("ldmatrix.sync.aligned.m8n8.x4.shared.b16 {%0,%1,%2,%3}, [%4];"
                 : "=r"(r[0]), "=r"(r[1]), "=r"(r[2]), "=r"(r[3]) : "r"(addr));
}
__device__ __forceinline__ void mma8(float* d, const uint32_t* a,
                                     const uint32_t* b) {
    asm volatile(
        "mma.sync.aligned.m16n8k8.row.col.f32.tf32.tf32.f32 "
        "{%0,%1,%2,%3}, {%4,%5,%6,%7}, {%8,%9}, {%0,%1,%2,%3};"
        : "+f"(d[0]), "+f"(d[1]), "+f"(d[2]), "+f"(d[3])
        : "r"(a[0]), "r"(a[1]), "r"(a[2]), "r"(a[3]), "r"(b[0]), "r"(b[1]));
}
__device__ __forceinline__ void cp16(uint32_t dst, const void* src) {
    asm volatile("cp.async.cg.shared.global [%0], [%1], 16;"
                 :: "r"(dst), "l"(src));
}
#define CP_COMMIT() asm volatile("cp.async.commit_group;" ::: "memory")
#define CP_WAIT(n)  asm volatile("cp.async.wait_group " #n ";" ::: "memory")

// ============================================================================
// tf32 cvt prep kernels
// ============================================================================
__global__ void cvt_kernel(const float4* __restrict__ src,
                           float4* __restrict__ dst, int n4) {
    int i = blockIdx.x * 256 + threadIdx.x;
    if (i < n4) {
        float4 v = src[i];
        v.x = to_tf32(v.x); v.y = to_tf32(v.y);
        v.z = to_tf32(v.z); v.w = to_tf32(v.w);
        dst[i] = v;
    }
}
__global__ void cvt4_kernel(const float4* __restrict__ s0,
                            const float4* __restrict__ s1,
                            const float4* __restrict__ s2,
                            const float4* __restrict__ s3,
                            float4* __restrict__ d0, float4* __restrict__ d1,
                            float4* __restrict__ d2, float4* __restrict__ d3,
                            int n4) {
    const float4* src = (blockIdx.y == 0) ? s0 : (blockIdx.y == 1) ? s1
                        : (blockIdx.y == 2) ? s2 : s3;
    float4* dst = (blockIdx.y == 0) ? d0 : (blockIdx.y == 1) ? d1
                  : (blockIdx.y == 2) ? d2 : d3;
    int i = blockIdx.x * 256 + threadIdx.x;
    if (i < n4) {
        float4 v = src[i];
        v.x = to_tf32(v.x); v.y = to_tf32(v.y);
        v.z = to_tf32(v.z); v.w = to_tf32(v.w);
        dst[i] = v;
    }
}

// ============================================================================
// GEMM: C = A(MxDM) @ W(DMxDM)^T. Inputs pre-tf32. BM x 128 tiles, BK=32,
// 256 thr (8 warps 2x4), 3-stage cp.async pipeline, 1 barrier per chunk.
// z==2 (V projection) writes transposed tf32 into g_vt instead of C.
// ============================================================================
template <int BM>
__global__ __launch_bounds__(256, 2) void gemm_tc(
    const float* __restrict__ A,
    const float* __restrict__ W0, const float* __restrict__ W1,
    const float* __restrict__ W2,
    float* __restrict__ C0, float* __restrict__ C1, float* __restrict__ C2) {
    const float* W = (blockIdx.z == 0) ? W0 : (blockIdx.z == 1) ? W1 : W2;
    float* C       = (blockIdx.z == 0) ? C0 : (blockIdx.z == 1) ? C1 : C2;

    constexpr int MT = BM / 32;
    constexpr int ABYTES = BM * 32 * 4;

    extern __shared__ __align__(16) float sm[];
    uint32_t smA = smem_u32(sm);
    uint32_t smB = smA + 3 * ABYTES;

    int tid = threadIdx.x, wid = tid >> 5, lane = tid & 31;
    int m0 = blockIdx.y * BM, n0 = blockIdx.x * 128;
    int wm = wid >> 2, wn = wid & 3;

    int t7 = lane & 7;
    int rowA = wm * (BM / 2) + t7 + ((lane >> 3) & 1) * 8;
    int cA   = (lane >> 4) & 1;
    int rxA  = rowA & 7;
    int rowB = wn * 32 + t7 + ((lane >> 4) & 1) * 8;
    int cB   = (lane >> 3) & 1;
    int rxB  = rowB & 7;

    const float* Ag = A + (size_t)m0 * DM;
    const float* Wg = W + (size_t)n0 * DM;

#define G_ISSUE(c)                                                          \
    do {                                                                    \
        int _buf = (c) % 3;                                                 \
        uint32_t _sa = smA + _buf * ABYTES;                                 \
        uint32_t _sb = smB + _buf * 16384;                                  \
        _Pragma("unroll") for (int i = 0; i < BM / 32; i++) {               \
            int idx = tid + i * 256;                                        \
            int r = idx >> 3, u = idx & 7;                                  \
            cp16(_sa + (r * 8 + (u ^ (r & 7))) * 16,                        \
                 Ag + (size_t)r * DM + (c) * 32 + u * 4);                   \
        }                                                                   \
        _Pragma("unroll") for (int i = 0; i < 4; i++) {                     \
            int idx = tid + i * 256;                                        \
            int r = idx >> 3, u = idx & 7;                                  \
            cp16(_sb + (r * 8 + (u ^ (r & 7))) * 16,                        \
                 Wg + (size_t)r * DM + (c) * 32 + u * 4);                   \
        }                                                                   \
    } while (0)

    G_ISSUE(0); CP_COMMIT();
    G_ISSUE(1); CP_COMMIT();

    float acc[MT][4][4];
#pragma unroll
    for (int i = 0; i < MT; i++)
#pragma unroll
        for (int j = 0; j < 4; j++)
#pragma unroll
            for (int e = 0; e < 4; e++) acc[i][j][e] = 0.0f;

    for (int c = 0; c < NCH; c++) {
        CP_WAIT(1);
        __syncthreads();
        if (c + 2 < NCH) G_ISSUE(c + 2);
        CP_COMMIT();

        int buf = c % 3;
        uint32_t Ab = smA + buf * ABYTES;
        uint32_t Bb = smB + buf * 16384;
#pragma unroll
        for (int ks = 0; ks < 4; ks++) {
            uint32_t af[MT][4], bf[2][4];
#pragma unroll
            for (int mt = 0; mt < MT; mt++)
                ldsm4(af[mt], Ab + ((rowA + mt * 16) * 8 +
                                    ((ks * 2 + cA) ^ rxA)) * 16);
#pragma unroll
            for (int np = 0; np < 2; np++)
                ldsm4(bf[np], Bb + ((rowB + np * 16) * 8 +
                                    ((ks * 2 + cB) ^ rxB)) * 16);
#pragma unroll
            for (int mt = 0; mt < MT; mt++)
#pragma unroll
                for (int nt = 0; nt < 4; nt++)
                    mma8(acc[mt][nt], af[mt], &bf[nt >> 1][(nt & 1) * 2]);
        }
    }

    int g = lane >> 2, tg = lane & 3;
    if (blockIdx.z == 2) {
        // V projection: write transposed tf32 into g_vt (bh, d, s)
#pragma unroll
        for (int mt = 0; mt < MT; mt++)
#pragma unroll
            for (int nt = 0; nt < 4; nt++)
#pragma unroll
                for (int half = 0; half < 2; half++) {
                    int row = m0 + wm * (BM / 2) + mt * 16 + g + half * 8;
                    int b = row >> 11, s = row & (SQ - 1);
                    int col = n0 + wn * 32 + nt * 8 + tg * 2;
                    int h = col >> 6, d = col & 63;
                    size_t base = ((size_t)((b * NH + h) * HD + d)) * SQ + s;
                    g_vt[base]      = to_tf32(acc[mt][nt][half * 2]);
                    g_vt[base + SQ] = to_tf32(acc[mt][nt][half * 2 + 1]);
                }
    } else {
#pragma unroll
        for (int mt = 0; mt < MT; mt++)
#pragma unroll
            for (int nt = 0; nt < 4; nt++)
#pragma unroll
                for (int half = 0; half < 2; half++) {
                    int row = m0 + wm * (BM / 2) + mt * 16 + g + half * 8;
                    int col = n0 + wn * 32 + nt * 8 + tg * 2;
                    float2 v = make_float2(acc[mt][nt][half * 2],
                                           acc[mt][nt][half * 2 + 1]);
                    *(float2*)&C[(size_t)row * DM + col] = v;
                }
    }
#undef G_ISSUE
}

// ---------------------------------------------------------------------------
// 2D RoPE in-place on g_q / g_k, writes tf32-rounded.
// ---------------------------------------------------------------------------
__global__ void rope_kernel(const int* __restrict__ row_ids,
                            const int* __restrict__ col_ids) {
    int idx = blockIdx.x * blockDim.x + threadIdx.x;
    float* buf = (blockIdx.y == 0) ? g_q : g_k;

    int p    = idx & 31;
    int bsh  = idx >> 5;
    int s    = (bsh / NH) & (SQ - 1);
    int half = p >> 4;
    int i    = p & 15;

    int pos = (half == 0) ? row_ids[s] : col_ids[s];
    float inv = expf(-(float)i * (9.210340371976184f / 16.0f));
    float ang = (float)pos * inv;
    float c, sn;
    sincosf(ang, &sn, &c);

    float* v = buf + (size_t)bsh * HD + half * 32;
    float x1 = v[i];
    float x2 = v[i + 16];
    v[i]      = to_tf32(x1 * c - x2 * sn);
    v[i + 16] = to_tf32(x2 * c + x1 * sn);
}

// ============================================================================
// Flash attention, tf32 mma.sync. CTA: 64q x 64k, 4 warps (16 q-rows each),
// cp.async double-buffered K/Vt, P repacked in registers (no P smem).
// smem: Q 16KB + K 2x16KB + Vt 2x16KB = 80KB -> 2 CTA/SM.
// grid: 768 1-D, heavy (large qt) first for causal balance.
// ============================================================================
#define ATT_SMEM 81920

__global__ __launch_bounds__(128, 2) void attn_tc() {
    extern __shared__ __align__(16) float sm[];
    uint32_t Qb    = smem_u32(sm);
    uint32_t Kbase = Qb + 16384;
    uint32_t Vbase = Qb + 49152;

    int tid = threadIdx.x, wid = tid >> 5, lane = tid & 31;
    int bx = blockIdx.x;
    int qt = (SQ / 64 - 1) - bx / (NB * NH);
    int bh = bx % (NB * NH);
    int b = bh / NH, h = bh % NH;

    const float* Qg  = g_q + ((size_t)(b * SQ + qt * 64)) * DM + h * HD;
    const float* Kg  = g_k + (size_t)b * SQ * DM + h * HD;
    const float* Vtg = g_vt + (size_t)bh * HD * SQ;

    int nkt = qt + 1;

#define KV_ISSUE(t)                                                         \
    do {                                                                    \
        if ((t) < nkt) {                                                    \
            int _k0 = (t) * 64;                                             \
            uint32_t _ks = Kbase + ((t) & 1) * 16384;                       \
            uint32_t _vs = Vbase + ((t) & 1) * 16384;                       \
            _Pragma("unroll") for (int i = 0; i < 8; i++) {                 \
                int idx = tid + i * 128;                                    \
                int r = idx >> 4, u = idx & 15;                             \
                cp16(_ks + (r * 16 + (u ^ (r & 7))) * 16,                   \
                     Kg + (size_t)(_k0 + r) * DM + u * 4);                  \
                cp16(_vs + (r * 16 + (u ^ (r & 7))) * 16,                   \
                     Vtg + (size_t)r * SQ + _k0 + u * 4);                   \
            }                                                               \
        }                                                                   \
    } while (0)

    KV_ISSUE(0); CP_COMMIT();

    // load Q (64x64), scaled by 1/8 (exact in tf32), swizzled
#pragma unroll
    for (int i = 0; i < 8; i++) {
        int idx = tid + i * 128;
        int r = idx >> 4, u = idx & 15;
        float4 v = *(const float4*)(Qg + (size_t)r * DM + u * 4);
        v.x *= 0.125f; v.y *= 0.125f; v.z *= 0.125f; v.w *= 0.125f;
        *(float4*)&sm[(r * 16 + (u ^ (r & 7))) * 4] = v;
    }

    int t7 = lane & 7, g = lane >> 2, tg = lane & 3;
    int rowA = wid * 16 + t7 + ((lane >> 3) & 1) * 8;
    int cA   = (lane >> 4) & 1;
    int rxA  = rowA & 7;
    int rowB = t7 + ((lane >> 4) & 1) * 8;
    int cB   = (lane >> 3) & 1;
    int rxB  = rowB & 7;

    int src0 = (lane & 28) | (tg >> 1);
    int src1 = src0 + 2;
    bool oddc = tg & 1;

    float o[8][4];
#pragma unroll
    for (int i = 0; i < 8; i++)
#pragma unroll
        for (int e = 0; e < 4; e++) o[i][e] = 0.0f;
    float m0r = -1e30f, m1r = -1e30f, l0 = 0.0f, l1 = 0.0f;

    int qwarp = qt * 64 + wid * 16;

    for (int t = 0; t < nkt; t++) {
        int k0 = t * 64;
        CP_WAIT(0);
        __syncthreads();
        KV_ISSUE(t + 1); CP_COMMIT();

        uint32_t Kb = Kbase + (t & 1) * 16384;
        uint32_t Vb = Vbase + (t & 1) * 16384;

        float s[8][4];
#pragma unroll
        for (int i = 0; i < 8; i++)
#pragma unroll
            for (int e = 0; e < 4; e++) s[i][e] = 0.0f;

#pragma unroll
        for (int ks = 0; ks < 8; ks++) {
            uint32_t aq[4], bk[4][4];
            ldsm4(aq, Qb + (rowA * 16 + ((ks * 2 + cA) ^ rxA)) * 16);
#pragma unroll
            for (int np = 0; np < 4; np++)
                ldsm4(bk[np], Kb + ((rowB + np * 16) * 16 +
                                    ((ks * 2 + cB) ^ rxB)) * 16);
#pragma unroll
            for (int nt = 0; nt < 8; nt++)
                mma8(s[nt], aq, &bk[nt >> 1][(nt & 1) * 2]);
        }

        // causal mask (only boundary tiles)
        if (k0 + 63 > qwarp) {
#pragma unroll
            for (int nt = 0; nt < 8; nt++)
#pragma unroll
                for (int e = 0; e < 4; e++) {
                    int colg = k0 + nt * 8 + tg * 2 + (e & 1);
                    int rowg = qwarp + g + (e >> 1) * 8;
                    if (colg > rowg) s[nt][e] = -1e30f;
                }
        }

        // online softmax (rows g and g+8)
        float rm0 = -1e30f, rm1 = -1e30f;
#pragma unroll
        for (int nt = 0; nt < 8; nt++) {
            rm0 = fmaxf(rm0, fmaxf(s[nt][0], s[nt][1]));
            rm1 = fmaxf(rm1, fmaxf(s[nt][2], s[nt][3]));
        }
        rm0 = fmaxf(rm0, __shfl_xor_sync(0xffffffffu, rm0, 1));
        rm0 = fmaxf(rm0, __shfl_xor_sync(0xffffffffu, rm0, 2));
        rm1 = fmaxf(rm1, __shfl_xor_sync(0xffffffffu, rm1, 1));
        rm1 = fmaxf(rm1, __shfl_xor_sync(0xffffffffu, rm1, 2));
        float mn0 = fmaxf(m0r, rm0), mn1 = fmaxf(m1r, rm1);
        float al0 = __expf(m0r - mn0), al1 = __expf(m1r - mn1);
        m0r = mn0; m1r = mn1;
        float rs0 = 0.0f, rs1 = 0.0f;
#pragma unroll
        for (int nt = 0; nt < 8; nt++) {
            float p0 = __expf(s[nt][0] - mn0);
            float p1 = __expf(s[nt][1] - mn0);
            float p2 = __expf(s[nt][2] - mn1);
            float p3 = __expf(s[nt][3] - mn1);
            rs0 += p0 + p1;
            rs1 += p2 + p3;
            s[nt][0] = to_tf32(p0); s[nt][1] = to_tf32(p1);
            s[nt][2] = to_tf32(p2); s[nt][3] = to_tf32(p3);
        }
        l0 = l0 * al0 + rs0;
        l1 = l1 * al1 + rs1;
#pragma unroll
        for (int nt = 0; nt < 8; nt++) {
            o[nt][0] *= al0; o[nt][1] *= al0;
            o[nt][2] *= al1; o[nt][3] *= al1;
        }

        // PV: repack P C-frag -> A-frag via shuffles, mma against Vt
#pragma unroll
        for (int kb = 0; kb < 8; kb++) {
            float v00 = __shfl_sync(0xffffffffu, s[kb][0], src0);
            float v01 = __shfl_sync(0xffffffffu, s[kb][1], src0);
            float v10 = __shfl_sync(0xffffffffu, s[kb][2], src0);
            float v11 = __shfl_sync(0xffffffffu, s[kb][3], src0);
            float w00 = __shfl_sync(0xffffffffu, s[kb][0], src1);
            float w01 = __shfl_sync(0xffffffffu, s[kb][1], src1);
            float w10 = __shfl_sync(0xffffffffu, s[kb][2], src1);
            float w11 = __shfl_sync(0xffffffffu, s[kb][3], src1);
            uint32_t ap[4];
            ap[0] = __float_as_uint(oddc ? v01 : v00);
            ap[1] = __float_as_uint(oddc ? v11 : v10);
            ap[2] = __float_as_uint(oddc ? w01 : w00);
            ap[3] = __float_as_uint(oddc ? w11 : w10);
            uint32_t bv[4][4];
#pragma unroll
            for (int np = 0; np < 4; np++)
                ldsm4(bv[np], Vb + ((rowB + np * 16) * 16 +
                                    ((kb * 2 + cB) ^ rxB)) * 16);
#pragma unroll
            for (int nt = 0; nt < 8; nt++)
                mma8(o[nt], ap, &bv[nt >> 1][(nt & 1) * 2]);
        }
    }

    // final: reduce l, normalize, store tf32 to g_attn
    l0 += __shfl_xor_sync(0xffffffffu, l0, 1);
    l0 += __shfl_xor_sync(0xffffffffu, l0, 2);
    l1 += __shfl_xor_sync(0xffffffffu, l1, 1);
    l1 += __shfl_xor_sync(0xffffffffu, l1, 2);
    float inv0 = 1.0f / l0, inv1 = 1.0f / l1;

    float* Og = g_attn + ((size_t)(b * SQ + qt * 64 + wid * 16)) * DM + h * HD;
#pragma unroll
    for (int nt = 0; nt < 8; nt++) {
        int col = nt * 8 + tg * 2;
        float2 v0 = make_float2(to_tf32(o[nt][0] * inv0),
                                to_tf32(o[nt][1] * inv0));
        *(float2*)&Og[(size_t)g * DM + col] = v0;
        float2 v1 = make_float2(to_tf32(o[nt][2] * inv1),
                                to_tf32(o[nt][3] * inv1));
        *(float2*)&Og[(size_t)(g + 8) * DM + col] = v1;
    }
#undef KV_ISSUE
}

// ---------------------------------------------------------------------------
extern "C" void kernel_launch(void* const* d_in, const int* in_sizes, int n_in,
                              void* d_out, int out_size) {
    const float* x  = (const float*)d_in[0];
    const int* row  = (const int*)d_in[1];
    const int* col  = (const int*)d_in[2];
    const float* Wq = (const float*)d_in[3];
    const float* Wk = (const float*)d_in[4];
    const float* Wv = (const float*)d_in[5];
    const float* Wo = (const float*)d_in[6];
    float* out = (float*)d_out;

    void *qp, *kp, *ap, *xp, *wqp, *wkp, *wvp, *wop;
    cudaGetSymbolAddress(&qp, g_q);
    cudaGetSymbolAddress(&kp, g_k);
    cudaGetSymbolAddress(&ap, g_attn);
    cudaGetSymbolAddress(&xp, g_x);
    cudaGetSymbolAddress(&wqp, g_wq);
    cudaGetSymbolAddress(&wkp, g_wk);
    cudaGetSymbolAddress(&wvp, g_wv);
    cudaGetSymbolAddress(&wop, g_wo);

    cudaFuncSetAttribute(gemm_tc<128>,
                         cudaFuncAttributeMaxDynamicSharedMemorySize, 98304);
    cudaFuncSetAttribute(gemm_tc<64>,
                         cudaFuncAttributeMaxDynamicSharedMemorySize, 73728);
    cudaFuncSetAttribute(attn_tc,
                         cudaFuncAttributeMaxDynamicSharedMemorySize, ATT_SMEM);

    // 0) tf32 pre-conversion of x and weights (2 launches)
    int n4x = NB * SQ * DM / 4, n4w = DM * DM / 4;
    cvt_kernel<<<(n4x + 255) / 256, 256>>>((const float4*)x, (float4*)xp, n4x);
    cvt4_kernel<<<dim3((n4w + 255) / 256, 4), 256>>>(
        (const float4*)Wq, (const float4*)Wk, (const float4*)Wv,
        (const float4*)Wo,
        (float4*)wqp, (float4*)wkp, (float4*)wvp, (float4*)wop, n4w);

    // 1) fused QKV projections; z==2 writes V transposed tf32 into g_vt
    gemm_tc<128><<<dim3(DM / 128, (NB * SQ) / 128, 3), 256, 98304>>>(
        (const float*)xp, (const float*)wqp, (const float*)wkp,
        (const float*)wvp, (float*)qp, (float*)kp, nullptr);

    // 2) 2D RoPE (q,k -> tf32)
    rope_kernel<<<dim3((NB * SQ * NH * 32) / 256, 2), 256>>>(row, col);

    // 3) flash attention (64q-tiles, heavy first)
    attn_tc<<<(SQ / 64) * NB * NH, 128, ATT_SMEM>>>();

    // 4) output projection (BM=64 for grid balance)
    gemm_tc<64><<<dim3(DM / 128, (NB * SQ) / 64, 1), 256, 73728>>>(
        (const float*)ap, (const float*)wop, (const float*)wop,
        (const float*)wop, out, out, out);
}

// round 6
// speedup vs baseline: 8.1442x; 1.8293x over previous
#include <cuda_runtime.h>
#include <cuda_fp16.h>
#include <cstdint>
#include <math.h>

#define NB 2
#define NH 12
#define SQ 2048
#define HD 64
#define DM 768

// ---------------- scratch (device globals; no allocations allowed) ----------
__device__ __half g_q[NB * SQ * DM];          // (B,S,H*D) fp16, roped+scaled
__device__ __half g_k[NB * SQ * DM];          // fp16, roped
__device__ __half g_vt[NB * NH * HD * SQ];    // (bh, d, s) fp16
__device__ __half g_attn[NB * SQ * DM];       // fp16 attn out
__device__ __half g_x[NB * SQ * DM];          // fp16 x
__device__ __half g_wq[DM * DM], g_wk[DM * DM], g_wv[DM * DM], g_wo[DM * DM];
__device__ float2 g_tab[SQ * 32];             // (s, half, i) -> (cos, sin)

// ============================ helpers =======================================
__device__ __forceinline__ uint32_t smem_u32(const void* p) {
    uint32_t a;
    asm("{ .reg .u64 t; cvta.to.shared.u64 t, %1; cvt.u32.u64 %0, t; }"
        : "=r"(a) : "l"(p));
    return a;
}
__device__ __forceinline__ uint32_t f22h2(float a, float b) {
    __half2 h = __floats2half2_rn(a, b);
    return *reinterpret_cast<uint32_t*>(&h);
}
__device__ __forceinline__ void ldsm4(uint32_t* r, uint32_t addr) {
    asm volatile("ldmatrix.sync.aligned.m8n8.x4.shared.b16 {%0,%1,%2,%3}, [%4];"
                 : "=r"(r[0]), "=r"(r[1]), "=r"(r[2]), "=r"(r[3]) : "r"(addr));
}
__device__ __forceinline__ void mma16(float* d, const uint32_t* a,
                                      const uint32_t* b) {
    asm volatile(
        "mma.sync.aligned.m16n8k16.row.col.f32.f16.f16.f32 "
        "{%0,%1,%2,%3}, {%4,%5,%6,%7}, {%8,%9}, {%0,%1,%2,%3};"
        : "+f"(d[0]), "+f"(d[1]), "+f"(d[2]), "+f"(d[3])
        : "r"(a[0]), "r"(a[1]), "r"(a[2]), "r"(a[3]), "r"(b[0]), "r"(b[1]));
}
__device__ __forceinline__ void cp16(uint32_t dst, const void* src) {
    asm volatile("cp.async.cg.shared.global [%0], [%1], 16;"
                 :: "r"(dst), "l"(src));
}
#define CP_COMMIT() asm volatile("cp.async.commit_group;" ::: "memory")
#define CP_WAIT(n)  asm volatile("cp.async.wait_group " #n ";" ::: "memory")

// ============================================================================
// fp32 -> fp16 prep kernels
// ============================================================================
__global__ void cvtx_kernel(const float4* __restrict__ src,
                            uint2* __restrict__ dst, int n4) {
    int i = blockIdx.x * 256 + threadIdx.x;
    if (i < n4) {
        float4 v = src[i];
        dst[i] = make_uint2(f22h2(v.x, v.y), f22h2(v.z, v.w));
    }
}
__global__ void cvt4_kernel(const float4* __restrict__ s0,
                            const float4* __restrict__ s1,
                            const float4* __restrict__ s2,
                            const float4* __restrict__ s3,
                            uint2* __restrict__ d0, uint2* __restrict__ d1,
                            uint2* __restrict__ d2, uint2* __restrict__ d3,
                            int n4) {
    const float4* src = (blockIdx.y == 0) ? s0 : (blockIdx.y == 1) ? s1
                        : (blockIdx.y == 2) ? s2 : s3;
    uint2* dst = (blockIdx.y == 0) ? d0 : (blockIdx.y == 1) ? d1
                 : (blockIdx.y == 2) ? d2 : d3;
    int i = blockIdx.x * 256 + threadIdx.x;
    if (i < n4) {
        float4 v = src[i];
        dst[i] = make_uint2(f22h2(v.x, v.y), f22h2(v.z, v.w));
    }
}

// RoPE cos/sin table: g_tab[s*32 + half*16 + i]
__global__ void table_kernel(const int* __restrict__ row_ids,
                             const int* __restrict__ col_ids) {
    int idx = blockIdx.x * 256 + threadIdx.x;   // < SQ*32
    int s = idx >> 5, p = idx & 31;
    int half = p >> 4, i = p & 15;
    int pos = (half == 0) ? row_ids[s] : col_ids[s];
    float inv = expf(-(float)i * (9.210340371976184f / 16.0f));
    float ang = (float)pos * inv;
    float c, sn;
    sincosf(ang, &sn, &c);
    g_tab[idx] = make_float2(c, sn);
}

// ============================================================================
// fp16 GEMM: C = A(MxDM) @ W(DMxDM)^T. BM x 128 tiles, BK=64 (128B rows),
// 256 thr (8 warps 2x4), 3-stage cp.async, 1 barrier per chunk.
// OUT32: fp32 C (outproj). Else half C; z==2 writes transposed half to g_vt.
// ============================================================================
template <int BM, bool OUT32>
__global__ __launch_bounds__(256, 2) void gemm_h(
    const __half* __restrict__ A,
    const __half* __restrict__ W0, const __half* __restrict__ W1,
    const __half* __restrict__ W2,
    void* __restrict__ C0v, void* __restrict__ C1v, void* __restrict__ C2v) {
    const __half* W = (blockIdx.z == 0) ? W0 : (blockIdx.z == 1) ? W1 : W2;
    void* Cv        = (blockIdx.z == 0) ? C0v : (blockIdx.z == 1) ? C1v : C2v;

    constexpr int MT = BM / 32;
    constexpr int ASTAGE = BM * 128;   // bytes per A stage
    constexpr int NCH = DM / 64;       // 12 chunks

    extern __shared__ __align__(16) char smx[];
    uint32_t smA = smem_u32(smx);
    uint32_t smB = smA + 3 * ASTAGE;

    int tid = threadIdx.x, wid = tid >> 5, lane = tid & 31;
    int m0 = blockIdx.y * BM, n0 = blockIdx.x * 128;
    int wm = wid >> 2, wn = wid & 3;

    // fragment address pieces
    int rowAl = wm * (BM / 2) + (lane & 15);
    int cuA   = lane >> 4;                     // unit offset 0/1
    int rowBl = wn * 32 + ((lane >> 4) * 8) + (lane & 7);
    int cuB   = (lane >> 3) & 1;

    const __half* Ag = A + (size_t)m0 * DM;
    const __half* Wg = W + (size_t)n0 * DM;

#define G_ISSUE(c)                                                          \
    do {                                                                    \
        int _buf = (c) % 3;                                                 \
        uint32_t _sa = smA + _buf * ASTAGE;                                 \
        uint32_t _sb = smB + _buf * 16384;                                  \
        _Pragma("unroll") for (int i = 0; i < BM / 32; i++) {               \
            int idx = tid + i * 256;                                        \
            int r = idx >> 3, u = idx & 7;                                  \
            cp16(_sa + (r * 8 + (u ^ (r & 7))) * 16,                        \
                 Ag + (size_t)r * DM + (c) * 64 + u * 8);                   \
        }                                                                   \
        _Pragma("unroll") for (int i = 0; i < 4; i++) {                     \
            int idx = tid + i * 256;                                        \
            int r = idx >> 3, u = idx & 7;                                  \
            cp16(_sb + (r * 8 + (u ^ (r & 7))) * 16,                        \
                 Wg + (size_t)r * DM + (c) * 64 + u * 8);                   \
        }                                                                   \
    } while (0)

    G_ISSUE(0); CP_COMMIT();
    G_ISSUE(1); CP_COMMIT();

    float acc[MT][4][4];
#pragma unroll
    for (int i = 0; i < MT; i++)
#pragma unroll
        for (int j = 0; j < 4; j++)
#pragma unroll
            for (int e = 0; e < 4; e++) acc[i][j][e] = 0.0f;

    for (int c = 0; c < NCH; c++) {
        CP_WAIT(1);
        __syncthreads();
        if (c + 2 < NCH) G_ISSUE(c + 2);
        CP_COMMIT();

        int buf = c % 3;
        uint32_t Ab = smA + buf * ASTAGE;
        uint32_t Bb = smB + buf * 16384;
#pragma unroll
        for (int ks = 0; ks < 4; ks++) {
            uint32_t af[MT][4], bf[2][4];
#pragma unroll
            for (int mt = 0; mt < MT; mt++) {
                int rA = rowAl + mt * 16;
                ldsm4(af[mt], Ab + (rA * 8 + ((2 * ks + cuA) ^ (rA & 7))) * 16);
            }
#pragma unroll
            for (int np = 0; np < 2; np++) {
                int rB = rowBl + np * 16;
                ldsm4(bf[np], Bb + (rB * 8 + ((2 * ks + cuB) ^ (rB & 7))) * 16);
            }
#pragma unroll
            for (int mt = 0; mt < MT; mt++)
#pragma unroll
                for (int nt = 0; nt < 4; nt++)
                    mma16(acc[mt][nt], af[mt], &bf[nt >> 1][(nt & 1) * 2]);
        }
    }

    int g = lane >> 2, tg = lane & 3;
    if (OUT32) {
        float* C = (float*)Cv;
#pragma unroll
        for (int mt = 0; mt < MT; mt++)
#pragma unroll
            for (int nt = 0; nt < 4; nt++)
#pragma unroll
                for (int half = 0; half < 2; half++) {
                    int row = m0 + wm * (BM / 2) + mt * 16 + g + half * 8;
                    int col = n0 + wn * 32 + nt * 8 + tg * 2;
                    float2 v = make_float2(acc[mt][nt][half * 2],
                                           acc[mt][nt][half * 2 + 1]);
                    *(float2*)&C[(size_t)row * DM + col] = v;
                }
    } else if (blockIdx.z == 2) {
        // V projection: write transposed fp16 into g_vt (bh, d, s)
#pragma unroll
        for (int mt = 0; mt < MT; mt++)
#pragma unroll
            for (int nt = 0; nt < 4; nt++)
#pragma unroll
                for (int half = 0; half < 2; half++) {
                    int row = m0 + wm * (BM / 2) + mt * 16 + g + half * 8;
                    int b = row >> 11, s = row & (SQ - 1);
                    int col = n0 + wn * 32 + nt * 8 + tg * 2;
                    int h = col >> 6, d = col & 63;
                    size_t base = ((size_t)((b * NH + h) * HD + d)) * SQ + s;
                    g_vt[base]      = __float2half(acc[mt][nt][half * 2]);
                    g_vt[base + SQ] = __float2half(acc[mt][nt][half * 2 + 1]);
                }
    } else {
        __half* C = (__half*)Cv;
#pragma unroll
        for (int mt = 0; mt < MT; mt++)
#pragma unroll
            for (int nt = 0; nt < 4; nt++)
#pragma unroll
                for (int half = 0; half < 2; half++) {
                    int row = m0 + wm * (BM / 2) + mt * 16 + g + half * 8;
                    int col = n0 + wn * 32 + nt * 8 + tg * 2;
                    *(uint32_t*)&C[(size_t)row * DM + col] =
                        f22h2(acc[mt][nt][half * 2], acc[mt][nt][half * 2 + 1]);
                }
    }
#undef G_ISSUE
}

// ---------------------------------------------------------------------------
// 2D RoPE on fp16 q/k using precomputed table; q additionally scaled by 1/8.
// ---------------------------------------------------------------------------
__global__ void rope_kernel() {
    int idx = blockIdx.x * 256 + threadIdx.x;   // < NB*SQ*NH*32
    __half* buf = (blockIdx.y == 0) ? g_q : g_k;
    float scale = (blockIdx.y == 0) ? 0.125f : 1.0f;

    int p    = idx & 31;
    int bsh  = idx >> 5;
    int s    = (bsh / NH) & (SQ - 1);
    int half = p >> 4;
    int i    = p & 15;

    float2 cs = g_tab[s * 32 + half * 16 + i];
    __half* v = buf + (size_t)bsh * HD + half * 32;
    float x1 = __half2float(v[i]);
    float x2 = __half2float(v[i + 16]);
    v[i]      = __float2half((x1 * cs.x - x2 * cs.y) * scale);
    v[i + 16] = __float2half((x2 * cs.x + x1 * cs.y) * scale);
}

// ============================================================================
// Flash attention, fp16 mma m16n8k16. CTA: 64q x 64k, 4 warps (16 q each).
// cp.async double-buffered K/Vt; P C-frag -> A-frag by half2 packing (free).
// smem: Q 8KB + K 2x8KB + Vt 2x8KB = 40KB -> 3 CTA/SM.
// ============================================================================
#define ATT_SMEM 40960

__global__ __launch_bounds__(128, 3) void attn_h() {
    extern __shared__ __align__(16) char smx[];
    uint32_t Qb    = smem_u32(smx);
    uint32_t Kbase = Qb + 8192;
    uint32_t Vbase = Qb + 24576;

    int tid = threadIdx.x, wid = tid >> 5, lane = tid & 31;
    int bx = blockIdx.x;
    int qt = (SQ / 64 - 1) - bx / (NB * NH);
    int bh = bx % (NB * NH);
    int b = bh / NH, h = bh % NH;

    const __half* Qg  = g_q + ((size_t)(b * SQ + qt * 64)) * DM + h * HD;
    const __half* Kg  = g_k + (size_t)b * SQ * DM + h * HD;
    const __half* Vtg = g_vt + (size_t)bh * HD * SQ;

    int nkt = qt + 1;

#define KV_ISSUE(t)                                                         \
    do {                                                                    \
        if ((t) < nkt) {                                                    \
            int _k0 = (t) * 64;                                             \
            uint32_t _ks = Kbase + ((t) & 1) * 8192;                        \
            uint32_t _vs = Vbase + ((t) & 1) * 8192;                        \
            _Pragma("unroll") for (int i = 0; i < 4; i++) {                 \
                int idx = tid + i * 128;                                    \
                int r = idx >> 3, u = idx & 7;                              \
                cp16(_ks + (r * 8 + (u ^ (r & 7))) * 16,                    \
                     Kg + (size_t)(_k0 + r) * DM + u * 8);                  \
                cp16(_vs + (r * 8 + (u ^ (r & 7))) * 16,                    \
                     Vtg + (size_t)r * SQ + _k0 + u * 8);                   \
            }                                                               \
        }                                                                   \
    } while (0)

    KV_ISSUE(0); CP_COMMIT();
    // Q tile via cp.async (already scaled in rope)
#pragma unroll
    for (int i = 0; i < 4; i++) {
        int idx = tid + i * 128;
        int r = idx >> 3, u = idx & 7;
        cp16(Qb + (r * 8 + (u ^ (r & 7))) * 16, Qg + (size_t)r * DM + u * 8);
    }
    CP_COMMIT();
    CP_WAIT(0);
    __syncthreads();

    int rowAl = wid * 16 + (lane & 15);
    int cuA   = lane >> 4;
    int rowBl = ((lane >> 4) * 8) + (lane & 7);
    int cuB   = (lane >> 3) & 1;
    int g = lane >> 2, tg = lane & 3;

    // preload Q fragments (Q is never overwritten)
    uint32_t aq[4][4];
#pragma unroll
    for (int ks = 0; ks < 4; ks++)
        ldsm4(aq[ks], Qb + (rowAl * 8 + ((2 * ks + cuA) ^ (rowAl & 7))) * 16);

    float o[8][4];
#pragma unroll
    for (int i = 0; i < 8; i++)
#pragma unroll
        for (int e = 0; e < 4; e++) o[i][e] = 0.0f;
    float m0r = -1e30f, m1r = -1e30f, l0 = 0.0f, l1 = 0.0f;

    int qwarp = qt * 64 + wid * 16;

    for (int t = 0; t < nkt; t++) {
        int k0 = t * 64;
        // buffers: tile t resident & synced at loop entry
        KV_ISSUE(t + 1); CP_COMMIT();

        uint32_t Kb = Kbase + (t & 1) * 8192;
        uint32_t Vb = Vbase + (t & 1) * 8192;

        // S = Q K^T (scale pre-folded into Q)
        float s[8][4];
#pragma unroll
        for (int i = 0; i < 8; i++)
#pragma unroll
            for (int e = 0; e < 4; e++) s[i][e] = 0.0f;

#pragma unroll
        for (int ks = 0; ks < 4; ks++) {
            uint32_t bk[4][4];
#pragma unroll
            for (int np = 0; np < 4; np++) {
                int rB = rowBl + np * 16;
                ldsm4(bk[np], Kb + (rB * 8 + ((2 * ks + cuB) ^ (rB & 7))) * 16);
            }
#pragma unroll
            for (int nt = 0; nt < 8; nt++)
                mma16(s[nt], aq[ks], &bk[nt >> 1][(nt & 1) * 2]);
        }

        // causal mask (boundary tiles only)
        if (k0 + 63 > qwarp) {
#pragma unroll
            for (int nt = 0; nt < 8; nt++)
#pragma unroll
                for (int e = 0; e < 4; e++) {
                    int colg = k0 + nt * 8 + tg * 2 + (e & 1);
                    int rowg = qwarp + g + (e >> 1) * 8;
                    if (colg > rowg) s[nt][e] = -1e30f;
                }
        }

        // online softmax (rows g, g+8)
        float rm0 = -1e30f, rm1 = -1e30f;
#pragma unroll
        for (int nt = 0; nt < 8; nt++) {
            rm0 = fmaxf(rm0, fmaxf(s[nt][0], s[nt][1]));
            rm1 = fmaxf(rm1, fmaxf(s[nt][2], s[nt][3]));
        }
        rm0 = fmaxf(rm0, __shfl_xor_sync(0xffffffffu, rm0, 1));
        rm0 = fmaxf(rm0, __shfl_xor_sync(0xffffffffu, rm0, 2));
        rm1 = fmaxf(rm1, __shfl_xor_sync(0xffffffffu, rm1, 1));
        rm1 = fmaxf(rm1, __shfl_xor_sync(0xffffffffu, rm1, 2));
        float mn0 = fmaxf(m0r, rm0), mn1 = fmaxf(m1r, rm1);
        float al0 = __expf(m0r - mn0), al1 = __expf(m1r - mn1);
        m0r = mn0; m1r = mn1;
        float rs0 = 0.0f, rs1 = 0.0f;
#pragma unroll
        for (int nt = 0; nt < 8; nt++) {
            s[nt][0] = __expf(s[nt][0] - mn0);
            s[nt][1] = __expf(s[nt][1] - mn0);
            s[nt][2] = __expf(s[nt][2] - mn1);
            s[nt][3] = __expf(s[nt][3] - mn1);
            rs0 += s[nt][0] + s[nt][1];
            rs1 += s[nt][2] + s[nt][3];
        }
        l0 = l0 * al0 + rs0;
        l1 = l1 * al1 + rs1;
#pragma unroll
        for (int nt = 0; nt < 8; nt++) {
            o[nt][0] *= al0; o[nt][1] *= al0;
            o[nt][2] *= al1; o[nt][3] *= al1;
        }

        // PV: C-frag -> A-frag by half2 packing (no shuffles)
#pragma unroll
        for (int kb = 0; kb < 4; kb++) {
            uint32_t ap[4];
            ap[0] = f22h2(s[2 * kb][0],     s[2 * kb][1]);
            ap[1] = f22h2(s[2 * kb][2],     s[2 * kb][3]);
            ap[2] = f22h2(s[2 * kb + 1][0], s[2 * kb + 1][1]);
            ap[3] = f22h2(s[2 * kb + 1][2], s[2 * kb + 1][3]);
            uint32_t bv[4][4];
#pragma unroll
            for (int np = 0; np < 4; np++) {
                int rB = rowBl + np * 16;
                ldsm4(bv[np], Vb + (rB * 8 + ((2 * kb + cuB) ^ (rB & 7))) * 16);
            }
#pragma unroll
            for (int nt = 0; nt < 8; nt++)
                mma16(o[nt], ap, &bv[nt >> 1][(nt & 1) * 2]);
        }

        CP_WAIT(0);          // tile t+1 arrived
        __syncthreads();     // all warps done with tile t buffers
    }

    // reduce l, normalize, store fp16 to g_attn
    l0 += __shfl_xor_sync(0xffffffffu, l0, 1);
    l0 += __shfl_xor_sync(0xffffffffu, l0, 2);
    l1 += __shfl_xor_sync(0xffffffffu, l1, 1);
    l1 += __shfl_xor_sync(0xffffffffu, l1, 2);
    float inv0 = 1.0f / l0, inv1 = 1.0f / l1;

    __half* Og = g_attn + ((size_t)(b * SQ + qt * 64 + wid * 16)) * DM + h * HD;
#pragma unroll
    for (int nt = 0; nt < 8; nt++) {
        int col = nt * 8 + tg * 2;
        *(uint32_t*)&Og[(size_t)g * DM + col] =
            f22h2(o[nt][0] * inv0, o[nt][1] * inv0);
        *(uint32_t*)&Og[(size_t)(g + 8) * DM + col] =
            f22h2(o[nt][2] * inv1, o[nt][3] * inv1);
    }
#undef KV_ISSUE
}

// ---------------------------------------------------------------------------
extern "C" void kernel_launch(void* const* d_in, const int* in_sizes, int n_in,
                              void* d_out, int out_size) {
    const float* x  = (const float*)d_in[0];
    const int* row  = (const int*)d_in[1];
    const int* col  = (const int*)d_in[2];
    const float* Wq = (const float*)d_in[3];
    const float* Wk = (const float*)d_in[4];
    const float* Wv = (const float*)d_in[5];
    const float* Wo = (const float*)d_in[6];
    float* out = (float*)d_out;

    void *qp, *kp, *ap, *xp, *wqp, *wkp, *wvp, *wop;
    cudaGetSymbolAddress(&qp, g_q);
    cudaGetSymbolAddress(&kp, g_k);
    cudaGetSymbolAddress(&ap, g_attn);
    cudaGetSymbolAddress(&xp, g_x);
    cudaGetSymbolAddress(&wqp, g_wq);
    cudaGetSymbolAddress(&wkp, g_wk);
    cudaGetSymbolAddress(&wvp, g_wv);
    cudaGetSymbolAddress(&wop, g_wo);

    cudaFuncSetAttribute(gemm_h<128, false>,
                         cudaFuncAttributeMaxDynamicSharedMemorySize, 98304);
    cudaFuncSetAttribute(gemm_h<64, true>,
                         cudaFuncAttributeMaxDynamicSharedMemorySize, 73728);
    cudaFuncSetAttribute(attn_h,
                         cudaFuncAttributeMaxDynamicSharedMemorySize, ATT_SMEM);

    // 0) fp16 pre-conversion + rope table
    int n4x = NB * SQ * DM / 4, n4w = DM * DM / 4;
    cvtx_kernel<<<(n4x + 255) / 256, 256>>>((const float4*)x, (uint2*)xp, n4x);
    cvt4_kernel<<<dim3((n4w + 255) / 256, 4), 256>>>(
        (const float4*)Wq, (const float4*)Wk, (const float4*)Wv,
        (const float4*)Wo,
        (uint2*)wqp, (uint2*)wkp, (uint2*)wvp, (uint2*)wop, n4w);
    table_kernel<<<SQ * 32 / 256, 256>>>(row, col);

    // 1) fused QKV projections (fp16 mma); z==2 writes V transposed to g_vt
    gemm_h<128, false><<<dim3(DM / 128, (NB * SQ) / 128, 3), 256, 98304>>>(
        (const __half*)xp, (const __half*)wqp, (const __half*)wkp,
        (const __half*)wvp, qp, kp, nullptr);

    // 2) 2D RoPE (table-based; q scaled by 1/8)
    rope_kernel<<<dim3((NB * SQ * NH * 32) / 256, 2), 256>>>();

    // 3) flash attention (fp16, heavy-first)
    attn_h<<<(SQ / 64) * NB * NH, 128, ATT_SMEM>>>();

    // 4) output projection (fp32 out)
    gemm_h<64, true><<<dim3(DM / 128, (NB * SQ) / 64, 1), 256, 73728>>>(
        (const __half*)ap, (const __half*)wop, (const __half*)wop,
        (const __half*)wop, out, out, out);
}

// round 7
// speedup vs baseline: 8.5420x; 1.0489x over previous
#include <cuda_runtime.h>
#include <cuda_fp16.h>
#include <cstdint>
#include <math.h>

#define NB 2
#define NH 12
#define SQ 2048
#define HD 64
#define DM 768

// ---------------- scratch (device globals; no allocations allowed) ----------
__device__ __half g_q[NB * SQ * DM];          // (B,S,H*D) fp16, roped+scaled
__device__ __half g_k[NB * SQ * DM];          // fp16, roped
__device__ __half g_vt[NB * NH * HD * SQ];    // (bh, d, s) fp16
__device__ __half g_attn[NB * SQ * DM];       // fp16 attn out
__device__ __half g_x[NB * SQ * DM];          // fp16 x
__device__ __half g_wq[DM * DM], g_wk[DM * DM], g_wv[DM * DM], g_wo[DM * DM];
__device__ float2 g_tab[SQ * 32];             // (s, half, i) -> (cos, sin)

// ============================ helpers =======================================
__device__ __forceinline__ uint32_t smem_u32(const void* p) {
    uint32_t a;
    asm("{ .reg .u64 t; cvta.to.shared.u64 t, %1; cvt.u32.u64 %0, t; }"
        : "=r"(a) : "l"(p));
    return a;
}
__device__ __forceinline__ uint32_t f22h2(float a, float b) {
    __half2 h = __floats2half2_rn(a, b);
    return *reinterpret_cast<uint32_t*>(&h);
}
__device__ __forceinline__ void ldsm4(uint32_t* r, uint32_t addr) {
    asm volatile("ldmatrix.sync.aligned.m8n8.x4.shared.b16 {%0,%1,%2,%3}, [%4];"
                 : "=r"(r[0]), "=r"(r[1]), "=r"(r[2]), "=r"(r[3]) : "r"(addr));
}
__device__ __forceinline__ void mma16(float* d, const uint32_t* a,
                                      const uint32_t* b) {
    asm volatile(
        "mma.sync.aligned.m16n8k16.row.col.f32.f16.f16.f32 "
        "{%0,%1,%2,%3}, {%4,%5,%6,%7}, {%8,%9}, {%0,%1,%2,%3};"
        : "+f"(d[0]), "+f"(d[1]), "+f"(d[2]), "+f"(d[3])
        : "r"(a[0]), "r"(a[1]), "r"(a[2]), "r"(a[3]), "r"(b[0]), "r"(b[1]));
}
__device__ __forceinline__ void cp16(uint32_t dst, const void* src) {
    asm volatile("cp.async.cg.shared.global [%0], [%1], 16;"
                 :: "r"(dst), "l"(src));
}
#define CP_COMMIT() asm volatile("cp.async.commit_group;" ::: "memory")
#define CP_WAIT(n)  asm volatile("cp.async.wait_group " #n ";" ::: "memory")

// ============================================================================
// prep kernels: fp32 -> fp16 conversion + rope table
// ============================================================================
__global__ void cvtx_kernel(const float4* __restrict__ src,
                            uint2* __restrict__ dst, int n4) {
    int i = blockIdx.x * 256 + threadIdx.x;
    if (i < n4) {
        float4 v = src[i];
        dst[i] = make_uint2(f22h2(v.x, v.y), f22h2(v.z, v.w));
    }
}
__global__ void cvt4_kernel(const float4* __restrict__ s0,
                            const float4* __restrict__ s1,
                            const float4* __restrict__ s2,
                            const float4* __restrict__ s3,
                            uint2* __restrict__ d0, uint2* __restrict__ d1,
                            uint2* __restrict__ d2, uint2* __restrict__ d3,
                            int n4) {
    const float4* src = (blockIdx.y == 0) ? s0 : (blockIdx.y == 1) ? s1
                        : (blockIdx.y == 2) ? s2 : s3;
    uint2* dst = (blockIdx.y == 0) ? d0 : (blockIdx.y == 1) ? d1
                 : (blockIdx.y == 2) ? d2 : d3;
    int i = blockIdx.x * 256 + threadIdx.x;
    if (i < n4) {
        float4 v = src[i];
        dst[i] = make_uint2(f22h2(v.x, v.y), f22h2(v.z, v.w));
    }
}
// RoPE cos/sin table: g_tab[s*32 + half*16 + i]
__global__ void table_kernel(const int* __restrict__ row_ids,
                             const int* __restrict__ col_ids) {
    int idx = blockIdx.x * 256 + threadIdx.x;   // < SQ*32
    int s = idx >> 5, p = idx & 31;
    int half = p >> 4, i = p & 15;
    int pos = (half == 0) ? row_ids[s] : col_ids[s];
    float inv = expf(-(float)i * (9.210340371976184f / 16.0f));
    float ang = (float)pos * inv;
    float c, sn;
    sincosf(ang, &sn, &c);
    g_tab[idx] = make_float2(c, sn);
}

// ============================================================================
// fp16 GEMM: C = A(MxDM) @ W(DMxDM)^T. BM x 128 tiles, BK=64 (128B rows),
// 256 thr (8 warps 2x4), 3-stage cp.async, 1 barrier per chunk.
// OUT32: fp32 C (outproj). Else fp16 C with FUSED 2D-RoPE in epilogue
// (z==0: q with 1/8 scale, z==1: k); z==2 writes transposed fp16 to g_vt.
// RoPE pairing (i, i+16) within a 32-wide half == (nt, nt+2) in the same
// thread's accumulators, since the warp n-tile is exactly one 32-col half.
// ============================================================================
template <int BM, bool OUT32>
__global__ __launch_bounds__(256, 2) void gemm_h(
    const __half* __restrict__ A,
    const __half* __restrict__ W0, const __half* __restrict__ W1,
    const __half* __restrict__ W2,
    void* __restrict__ C0v, void* __restrict__ C1v, void* __restrict__ C2v) {
    const __half* W = (blockIdx.z == 0) ? W0 : (blockIdx.z == 1) ? W1 : W2;
    void* Cv        = (blockIdx.z == 0) ? C0v : (blockIdx.z == 1) ? C1v : C2v;

    constexpr int MT = BM / 32;
    constexpr int ASTAGE = BM * 128;   // bytes per A stage
    constexpr int NCH = DM / 64;       // 12 chunks

    extern __shared__ __align__(16) char smx[];
    uint32_t smA = smem_u32(smx);
    uint32_t smB = smA + 3 * ASTAGE;

    int tid = threadIdx.x, wid = tid >> 5, lane = tid & 31;
    int m0 = blockIdx.y * BM, n0 = blockIdx.x * 128;
    int wm = wid >> 2, wn = wid & 3;

    int rowAl = wm * (BM / 2) + (lane & 15);
    int cuA   = lane >> 4;
    int rowBl = wn * 32 + ((lane >> 4) * 8) + (lane & 7);
    int cuB   = (lane >> 3) & 1;

    const __half* Ag = A + (size_t)m0 * DM;
    const __half* Wg = W + (size_t)n0 * DM;

#define G_ISSUE(c)                                                          \
    do {                                                                    \
        int _buf = (c) % 3;                                                 \
        uint32_t _sa = smA + _buf * ASTAGE;                                 \
        uint32_t _sb = smB + _buf * 16384;                                  \
        _Pragma("unroll") for (int i = 0; i < BM / 32; i++) {               \
            int idx = tid + i * 256;                                        \
            int r = idx >> 3, u = idx & 7;                                  \
            cp16(_sa + (r * 8 + (u ^ (r & 7))) * 16,                        \
                 Ag + (size_t)r * DM + (c) * 64 + u * 8);                   \
        }                                                                   \
        _Pragma("unroll") for (int i = 0; i < 4; i++) {                     \
            int idx = tid + i * 256;                                        \
            int r = idx >> 3, u = idx & 7;                                  \
            cp16(_sb + (r * 8 + (u ^ (r & 7))) * 16,                        \
                 Wg + (size_t)r * DM + (c) * 64 + u * 8);                   \
        }                                                                   \
    } while (0)

    G_ISSUE(0); CP_COMMIT();
    G_ISSUE(1); CP_COMMIT();

    float acc[MT][4][4];
#pragma unroll
    for (int i = 0; i < MT; i++)
#pragma unroll
        for (int j = 0; j < 4; j++)
#pragma unroll
            for (int e = 0; e < 4; e++) acc[i][j][e] = 0.0f;

    for (int c = 0; c < NCH; c++) {
        CP_WAIT(1);
        __syncthreads();
        if (c + 2 < NCH) G_ISSUE(c + 2);
        CP_COMMIT();

        int buf = c % 3;
        uint32_t Ab = smA + buf * ASTAGE;
        uint32_t Bb = smB + buf * 16384;
#pragma unroll
        for (int ks = 0; ks < 4; ks++) {
            uint32_t af[MT][4], bf[2][4];
#pragma unroll
            for (int mt = 0; mt < MT; mt++) {
                int rA = rowAl + mt * 16;
                ldsm4(af[mt], Ab + (rA * 8 + ((2 * ks + cuA) ^ (rA & 7))) * 16);
            }
#pragma unroll
            for (int np = 0; np < 2; np++) {
                int rB = rowBl + np * 16;
                ldsm4(bf[np], Bb + (rB * 8 + ((2 * ks + cuB) ^ (rB & 7))) * 16);
            }
#pragma unroll
            for (int mt = 0; mt < MT; mt++)
#pragma unroll
                for (int nt = 0; nt < 4; nt++)
                    mma16(acc[mt][nt], af[mt], &bf[nt >> 1][(nt & 1) * 2]);
        }
    }

    int g = lane >> 2, tg = lane & 3;
    if (OUT32) {
        float* C = (float*)Cv;
#pragma unroll
        for (int mt = 0; mt < MT; mt++)
#pragma unroll
            for (int nt = 0; nt < 4; nt++)
#pragma unroll
                for (int half = 0; half < 2; half++) {
                    int row = m0 + wm * (BM / 2) + mt * 16 + g + half * 8;
                    int col = n0 + wn * 32 + nt * 8 + tg * 2;
                    float2 v = make_float2(acc[mt][nt][half * 2],
                                           acc[mt][nt][half * 2 + 1]);
                    *(float2*)&C[(size_t)row * DM + col] = v;
                }
    } else if (blockIdx.z == 2) {
        // V projection: write transposed fp16 into g_vt (bh, d, s)
#pragma unroll
        for (int mt = 0; mt < MT; mt++)
#pragma unroll
            for (int nt = 0; nt < 4; nt++)
#pragma unroll
                for (int half = 0; half < 2; half++) {
                    int row = m0 + wm * (BM / 2) + mt * 16 + g + half * 8;
                    int b = row >> 11, s = row & (SQ - 1);
                    int col = n0 + wn * 32 + nt * 8 + tg * 2;
                    int h = col >> 6, d = col & 63;
                    size_t base = ((size_t)((b * NH + h) * HD + d)) * SQ + s;
                    g_vt[base]      = __float2half(acc[mt][nt][half * 2]);
                    g_vt[base + SQ] = __float2half(acc[mt][nt][half * 2 + 1]);
                }
    } else {
        // q/k projection: fused 2D RoPE (+1/8 scale for q) in fp32, then fp16
        float scale = (blockIdx.z == 0) ? 0.125f : 1.0f;
        int halfIdx = wn & 1;    // warp n-tile == one 32-col rope half
#pragma unroll
        for (int mt = 0; mt < MT; mt++)
#pragma unroll
            for (int e = 0; e < 4; e++) {
                int row = m0 + wm * (BM / 2) + mt * 16 + g + (e >> 1) * 8;
                int s = row & (SQ - 1);
                const float2* tab = g_tab + s * 32 + halfIdx * 16;
#pragma unroll
                for (int nt = 0; nt < 2; nt++) {
                    int i = nt * 8 + tg * 2 + (e & 1);
                    float2 cs = tab[i];
                    float x1 = acc[mt][nt][e];
                    float x2 = acc[mt][nt + 2][e];
                    acc[mt][nt][e]     = (x1 * cs.x - x2 * cs.y) * scale;
                    acc[mt][nt + 2][e] = (x2 * cs.x + x1 * cs.y) * scale;
                }
            }
        __half* C = (__half*)Cv;
#pragma unroll
        for (int mt = 0; mt < MT; mt++)
#pragma unroll
            for (int nt = 0; nt < 4; nt++)
#pragma unroll
                for (int half = 0; half < 2; half++) {
                    int row = m0 + wm * (BM / 2) + mt * 16 + g + half * 8;
                    int col = n0 + wn * 32 + nt * 8 + tg * 2;
                    *(uint32_t*)&C[(size_t)row * DM + col] =
                        f22h2(acc[mt][nt][half * 2], acc[mt][nt][half * 2 + 1]);
                }
    }
#undef G_ISSUE
}

// ============================================================================
// Flash attention, fp16 mma m16n8k16. CTA: 64q x 64k, 4 warps (16 q each).
// cp.async double-buffered K/Vt; P C-frag -> A-frag by half2 packing (free).
// smem: Q 8KB + K 2x8KB + Vt 2x8KB = 40KB -> 3 CTA/SM.
// ============================================================================
#define ATT_SMEM 40960

__global__ __launch_bounds__(128, 3) void attn_h() {
    extern __shared__ __align__(16) char smx[];
    uint32_t Qb    = smem_u32(smx);
    uint32_t Kbase = Qb + 8192;
    uint32_t Vbase = Qb + 24576;

    int tid = threadIdx.x, wid = tid >> 5, lane = tid & 31;
    int bx = blockIdx.x;
    int qt = (SQ / 64 - 1) - bx / (NB * NH);
    int bh = bx % (NB * NH);
    int b = bh / NH, h = bh % NH;

    const __half* Qg  = g_q + ((size_t)(b * SQ + qt * 64)) * DM + h * HD;
    const __half* Kg  = g_k + (size_t)b * SQ * DM + h * HD;
    const __half* Vtg = g_vt + (size_t)bh * HD * SQ;

    int nkt = qt + 1;

#define KV_ISSUE(t)                                                         \
    do {                                                                    \
        if ((t) < nkt) {                                                    \
            int _k0 = (t) * 64;                                             \
            uint32_t _ks = Kbase + ((t) & 1) * 8192;                        \
            uint32_t _vs = Vbase + ((t) & 1) * 8192;                        \
            _Pragma("unroll") for (int i = 0; i < 4; i++) {                 \
                int idx = tid + i * 128;                                    \
                int r = idx >> 3, u = idx & 7;                              \
                cp16(_ks + (r * 8 + (u ^ (r & 7))) * 16,                    \
                     Kg + (size_t)(_k0 + r) * DM + u * 8);                  \
                cp16(_vs + (r * 8 + (u ^ (r & 7))) * 16,                    \
                     Vtg + (size_t)r * SQ + _k0 + u * 8);                   \
            }                                                               \
        }                                                                   \
    } while (0)

    KV_ISSUE(0); CP_COMMIT();
    // Q tile via cp.async (already roped+scaled)
#pragma unroll
    for (int i = 0; i < 4; i++) {
        int idx = tid + i * 128;
        int r = idx >> 3, u = idx & 7;
        cp16(Qb + (r * 8 + (u ^ (r & 7))) * 16, Qg + (size_t)r * DM + u * 8);
    }
    CP_COMMIT();
    CP_WAIT(0);
    __syncthreads();

    int rowAl = wid * 16 + (lane & 15);
    int cuA   = lane >> 4;
    int rowBl = ((lane >> 4) * 8) + (lane & 7);
    int cuB   = (lane >> 3) & 1;
    int g = lane >> 2, tg = lane & 3;

    uint32_t aq[4][4];
#pragma unroll
    for (int ks = 0; ks < 4; ks++)
        ldsm4(aq[ks], Qb + (rowAl * 8 + ((2 * ks + cuA) ^ (rowAl & 7))) * 16);

    float o[8][4];
#pragma unroll
    for (int i = 0; i < 8; i++)
#pragma unroll
        for (int e = 0; e < 4; e++) o[i][e] = 0.0f;
    float m0r = -1e30f, m1r = -1e30f, l0 = 0.0f, l1 = 0.0f;

    int qwarp = qt * 64 + wid * 16;

    for (int t = 0; t < nkt; t++) {
        int k0 = t * 64;
        KV_ISSUE(t + 1); CP_COMMIT();

        uint32_t Kb = Kbase + (t & 1) * 8192;
        uint32_t Vb = Vbase + (t & 1) * 8192;

        float s[8][4];
#pragma unroll
        for (int i = 0; i < 8; i++)
#pragma unroll
            for (int e = 0; e < 4; e++) s[i][e] = 0.0f;

#pragma unroll
        for (int ks = 0; ks < 4; ks++) {
            uint32_t bk[4][4];
#pragma unroll
            for (int np = 0; np < 4; np++) {
                int rB = rowBl + np * 16;
                ldsm4(bk[np], Kb + (rB * 8 + ((2 * ks + cuB) ^ (rB & 7))) * 16);
            }
#pragma unroll
            for (int nt = 0; nt < 8; nt++)
                mma16(s[nt], aq[ks], &bk[nt >> 1][(nt & 1) * 2]);
        }

        if (k0 + 63 > qwarp) {
#pragma unroll
            for (int nt = 0; nt < 8; nt++)
#pragma unroll
                for (int e = 0; e < 4; e++) {
                    int colg = k0 + nt * 8 + tg * 2 + (e & 1);
                    int rowg = qwarp + g + (e >> 1) * 8;
                    if (colg > rowg) s[nt][e] = -1e30f;
                }
        }

        float rm0 = -1e30f, rm1 = -1e30f;
#pragma unroll
        for (int nt = 0; nt < 8; nt++) {
            rm0 = fmaxf(rm0, fmaxf(s[nt][0], s[nt][1]));
            rm1 = fmaxf(rm1, fmaxf(s[nt][2], s[nt][3]));
        }
        rm0 = fmaxf(rm0, __shfl_xor_sync(0xffffffffu, rm0, 1));
        rm0 = fmaxf(rm0, __shfl_xor_sync(0xffffffffu, rm0, 2));
        rm1 = fmaxf(rm1, __shfl_xor_sync(0xffffffffu, rm1, 1));
        rm1 = fmaxf(rm1, __shfl_xor_sync(0xffffffffu, rm1, 2));
        float mn0 = fmaxf(m0r, rm0), mn1 = fmaxf(m1r, rm1);
        float al0 = __expf(m0r - mn0), al1 = __expf(m1r - mn1);
        m0r = mn0; m1r = mn1;
        float rs0 = 0.0f, rs1 = 0.0f;
#pragma unroll
        for (int nt = 0; nt < 8; nt++) {
            s[nt][0] = __expf(s[nt][0] - mn0);
            s[nt][1] = __expf(s[nt][1] - mn0);
            s[nt][2] = __expf(s[nt][2] - mn1);
            s[nt][3] = __expf(s[nt][3] - mn1);
            rs0 += s[nt][0] + s[nt][1];
            rs1 += s[nt][2] + s[nt][3];
        }
        l0 = l0 * al0 + rs0;
        l1 = l1 * al1 + rs1;
#pragma unroll
        for (int nt = 0; nt < 8; nt++) {
            o[nt][0] *= al0; o[nt][1] *= al0;
            o[nt][2] *= al1; o[nt][3] *= al1;
        }

#pragma unroll
        for (int kb = 0; kb < 4; kb++) {
            uint32_t ap[4];
            ap[0] = f22h2(s[2 * kb][0],     s[2 * kb][1]);
            ap[1] = f22h2(s[2 * kb][2],     s[2 * kb][3]);
            ap[2] = f22h2(s[2 * kb + 1][0], s[2 * kb + 1][1]);
            ap[3] = f22h2(s[2 * kb + 1][2], s[2 * kb + 1][3]);
            uint32_t bv[4][4];
#pragma unroll
            for (int np = 0; np < 4; np++) {
                int rB = rowBl + np * 16;
                ldsm4(bv[np], Vb + (rB * 8 + ((2 * kb + cuB) ^ (rB & 7))) * 16);
            }
#pragma unroll
            for (int nt = 0; nt < 8; nt++)
                mma16(o[nt], ap, &bv[nt >> 1][(nt & 1) * 2]);
        }

        CP_WAIT(0);
        __syncthreads();
    }

    l0 += __shfl_xor_sync(0xffffffffu, l0, 1);
    l0 += __shfl_xor_sync(0xffffffffu, l0, 2);
    l1 += __shfl_xor_sync(0xffffffffu, l1, 1);
    l1 += __shfl_xor_sync(0xffffffffu, l1, 2);
    float inv0 = 1.0f / l0, inv1 = 1.0f / l1;

    __half* Og = g_attn + ((size_t)(b * SQ + qt * 64 + wid * 16)) * DM + h * HD;
#pragma unroll
    for (int nt = 0; nt < 8; nt++) {
        int col = nt * 8 + tg * 2;
        *(uint32_t*)&Og[(size_t)g * DM + col] =
            f22h2(o[nt][0] * inv0, o[nt][1] * inv0);
        *(uint32_t*)&Og[(size_t)(g + 8) * DM + col] =
            f22h2(o[nt][2] * inv1, o[nt][3] * inv1);
    }
#undef KV_ISSUE
}

// ---------------------------------------------------------------------------
extern "C" void kernel_launch(void* const* d_in, const int* in_sizes, int n_in,
                              void* d_out, int out_size) {
    const float* x  = (const float*)d_in[0];
    const int* row  = (const int*)d_in[1];
    const int* col  = (const int*)d_in[2];
    const float* Wq = (const float*)d_in[3];
    const float* Wk = (const float*)d_in[4];
    const float* Wv = (const float*)d_in[5];
    const float* Wo = (const float*)d_in[6];
    float* out = (float*)d_out;

    void *qp, *kp, *ap, *xp, *wqp, *wkp, *wvp, *wop;
    cudaGetSymbolAddress(&qp, g_q);
    cudaGetSymbolAddress(&kp, g_k);
    cudaGetSymbolAddress(&ap, g_attn);
    cudaGetSymbolAddress(&xp, g_x);
    cudaGetSymbolAddress(&wqp, g_wq);
    cudaGetSymbolAddress(&wkp, g_wk);
    cudaGetSymbolAddress(&wvp, g_wv);
    cudaGetSymbolAddress(&wop, g_wo);

    cudaFuncSetAttribute(gemm_h<128, false>,
                         cudaFuncAttributeMaxDynamicSharedMemorySize, 98304);
    cudaFuncSetAttribute(gemm_h<64, true>,
                         cudaFuncAttributeMaxDynamicSharedMemorySize, 73728);
    cudaFuncSetAttribute(attn_h,
                         cudaFuncAttributeMaxDynamicSharedMemorySize, ATT_SMEM);

    // 0) fp16 pre-conversion + rope table (table needed by gemm epilogue)
    int n4x = NB * SQ * DM / 4, n4w = DM * DM / 4;
    cvtx_kernel<<<(n4x + 255) / 256, 256>>>((const float4*)x, (uint2*)xp, n4x);
    cvt4_kernel<<<dim3((n4w + 255) / 256, 4), 256>>>(
        (const float4*)Wq, (const float4*)Wk, (const float4*)Wv,
        (const float4*)Wo,
        (uint2*)wqp, (uint2*)wkp, (uint2*)wvp, (uint2*)wop, n4w);
    table_kernel<<<SQ * 32 / 256, 256>>>(row, col);

    // 1) fused QKV projections + RoPE epilogue; z==2 writes V^T to g_vt
    gemm_h<128, false><<<dim3(DM / 128, (NB * SQ) / 128, 3), 256, 98304>>>(
        (const __half*)xp, (const __half*)wqp, (const __half*)wkp,
        (const __half*)wvp, qp, kp, nullptr);

    // 2) flash attention (fp16, heavy-first)
    attn_h<<<(SQ / 64) * NB * NH, 128, ATT_SMEM>>>();

    // 3) output projection (fp32 out)
    gemm_h<64, true><<<dim3(DM / 128, (NB * SQ) / 64, 1), 256, 73728>>>(
        (const __half*)ap, (const __half*)wop, (const __half*)wop,
        (const __half*)wop, out, out, out);
}

// round 8
// speedup vs baseline: 8.5724x; 1.0036x over previous
#include <cuda_runtime.h>
#include <cuda_fp16.h>
#include <cstdint>
#include <math.h>

#define NB 2
#define NH 12
#define SQ 2048
#define HD 64
#define DM 768

// ---------------- scratch (device globals; no allocations allowed) ----------
__device__ __half g_q[NB * SQ * DM];          // (B,S,H*D) fp16, roped+scaled
__device__ __half g_k[NB * SQ * DM];          // fp16, roped
__device__ __half g_vt[NB * NH * HD * SQ];    // (bh, d, s) fp16
__device__ __half g_attn[NB * SQ * DM];       // fp16 attn out
__device__ __half g_x[NB * SQ * DM];          // fp16 x
__device__ __half g_wq[DM * DM], g_wk[DM * DM], g_wv[DM * DM], g_wo[DM * DM];
__device__ float2 g_tab[SQ * 32];             // (s, half, i) -> (cos, sin)

// ============================ helpers =======================================
__device__ __forceinline__ uint32_t smem_u32(const void* p) {
    uint32_t a;
    asm("{ .reg .u64 t; cvta.to.shared.u64 t, %1; cvt.u32.u64 %0, t; }"
        : "=r"(a) : "l"(p));
    return a;
}
__device__ __forceinline__ uint32_t f22h2(float a, float b) {
    __half2 h = __floats2half2_rn(a, b);
    return *reinterpret_cast<uint32_t*>(&h);
}
__device__ __forceinline__ void ldsm4(uint32_t* r, uint32_t addr) {
    asm volatile("ldmatrix.sync.aligned.m8n8.x4.shared.b16 {%0,%1,%2,%3}, [%4];"
                 : "=r"(r[0]), "=r"(r[1]), "=r"(r[2]), "=r"(r[3]) : "r"(addr));
}
__device__ __forceinline__ void mma16(float* d, const uint32_t* a,
                                      const uint32_t* b) {
    asm volatile(
        "mma.sync.aligned.m16n8k16.row.col.f32.f16.f16.f32 "
        "{%0,%1,%2,%3}, {%4,%5,%6,%7}, {%8,%9}, {%0,%1,%2,%3};"
        : "+f"(d[0]), "+f"(d[1]), "+f"(d[2]), "+f"(d[3])
        : "r"(a[0]), "r"(a[1]), "r"(a[2]), "r"(a[3]), "r"(b[0]), "r"(b[1]));
}
__device__ __forceinline__ void cp16(uint32_t dst, const void* src) {
    asm volatile("cp.async.cg.shared.global [%0], [%1], 16;"
                 :: "r"(dst), "l"(src));
}
#define CP_COMMIT() asm volatile("cp.async.commit_group;" ::: "memory")
#define CP_WAIT(n)  asm volatile("cp.async.wait_group " #n ";" ::: "memory")

// ============================================================================
// Fused prep: x->fp16 | 4 weights->fp16 | rope table, one launch.
// blocks [0,3072): x   [3072,5376): weights (576 each)   [5376,5632): table
// ============================================================================
#define XBLK (NB * SQ * DM / 4 / 256)          // 3072
#define WBLK (DM * DM / 4 / 256)               // 576
#define TBLK (SQ * 32 / 256)                   // 256
__global__ void prep_kernel(const float4* __restrict__ x,
                            const float4* __restrict__ wq,
                            const float4* __restrict__ wk,
                            const float4* __restrict__ wv,
                            const float4* __restrict__ wo,
                            const int* __restrict__ row_ids,
                            const int* __restrict__ col_ids,
                            uint2* __restrict__ dx,
                            uint2* __restrict__ dwq, uint2* __restrict__ dwk,
                            uint2* __restrict__ dwv, uint2* __restrict__ dwo) {
    int blk = blockIdx.x;
    if (blk < XBLK) {
        int i = blk * 256 + threadIdx.x;
        float4 v = x[i];
        dx[i] = make_uint2(f22h2(v.x, v.y), f22h2(v.z, v.w));
    } else if (blk < XBLK + 4 * WBLK) {
        int w = (blk - XBLK) / WBLK;
        int i = ((blk - XBLK) % WBLK) * 256 + threadIdx.x;
        const float4* s = (w == 0) ? wq : (w == 1) ? wk : (w == 2) ? wv : wo;
        uint2* d        = (w == 0) ? dwq : (w == 1) ? dwk : (w == 2) ? dwv : dwo;
        float4 v = s[i];
        d[i] = make_uint2(f22h2(v.x, v.y), f22h2(v.z, v.w));
    } else {
        int idx = (blk - XBLK - 4 * WBLK) * 256 + threadIdx.x;   // < SQ*32
        int s = idx >> 5, p = idx & 31;
        int half = p >> 4, i = p & 15;
        int pos = (half == 0) ? row_ids[s] : col_ids[s];
        float inv = expf(-(float)i * (9.210340371976184f / 16.0f));
        float ang = (float)pos * inv;
        float c, sn;
        sincosf(ang, &sn, &c);
        g_tab[idx] = make_float2(c, sn);
    }
}

// ============================================================================
// fp16 GEMM: C = A(MxDM) @ W(DMxDM)^T. BM x 128 tiles, BK=64 (128B rows),
// 256 thr (8 warps 2x4), 3-stage cp.async, 1 barrier per chunk.
// OUT32: fp32 C (outproj). Else fp16 C with FUSED 2D-RoPE in epilogue
// (z==0: q with 1/8 scale, z==1: k); z==2 writes transposed fp16 to g_vt.
// ============================================================================
template <int BM, bool OUT32>
__global__ __launch_bounds__(256, 2) void gemm_h(
    const __half* __restrict__ A,
    const __half* __restrict__ W0, const __half* __restrict__ W1,
    const __half* __restrict__ W2,
    void* __restrict__ C0v, void* __restrict__ C1v, void* __restrict__ C2v) {
    const __half* W = (blockIdx.z == 0) ? W0 : (blockIdx.z == 1) ? W1 : W2;
    void* Cv        = (blockIdx.z == 0) ? C0v : (blockIdx.z == 1) ? C1v : C2v;

    constexpr int MT = BM / 32;
    constexpr int ASTAGE = BM * 128;   // bytes per A stage
    constexpr int NCH = DM / 64;       // 12 chunks

    extern __shared__ __align__(16) char smx[];
    uint32_t smA = smem_u32(smx);
    uint32_t smB = smA + 3 * ASTAGE;

    int tid = threadIdx.x, wid = tid >> 5, lane = tid & 31;
    int m0 = blockIdx.y * BM, n0 = blockIdx.x * 128;
    int wm = wid >> 2, wn = wid & 3;

    int rowAl = wm * (BM / 2) + (lane & 15);
    int cuA   = lane >> 4;
    int rowBl = wn * 32 + ((lane >> 4) * 8) + (lane & 7);
    int cuB   = (lane >> 3) & 1;

    const __half* Ag = A + (size_t)m0 * DM;
    const __half* Wg = W + (size_t)n0 * DM;

#define G_ISSUE(c)                                                          \
    do {                                                                    \
        int _buf = (c) % 3;                                                 \
        uint32_t _sa = smA + _buf * ASTAGE;                                 \
        uint32_t _sb = smB + _buf * 16384;                                  \
        _Pragma("unroll") for (int i = 0; i < BM / 32; i++) {               \
            int idx = tid + i * 256;                                        \
            int r = idx >> 3, u = idx & 7;                                  \
            cp16(_sa + (r * 8 + (u ^ (r & 7))) * 16,                        \
                 Ag + (size_t)r * DM + (c) * 64 + u * 8);                   \
        }                                                                   \
        _Pragma("unroll") for (int i = 0; i < 4; i++) {                     \
            int idx = tid + i * 256;                                        \
            int r = idx >> 3, u = idx & 7;                                  \
            cp16(_sb + (r * 8 + (u ^ (r & 7))) * 16,                        \
                 Wg + (size_t)r * DM + (c) * 64 + u * 8);                   \
        }                                                                   \
    } while (0)

    G_ISSUE(0); CP_COMMIT();
    G_ISSUE(1); CP_COMMIT();

    float acc[MT][4][4];
#pragma unroll
    for (int i = 0; i < MT; i++)
#pragma unroll
        for (int j = 0; j < 4; j++)
#pragma unroll
            for (int e = 0; e < 4; e++) acc[i][j][e] = 0.0f;

    for (int c = 0; c < NCH; c++) {
        CP_WAIT(1);
        __syncthreads();
        if (c + 2 < NCH) G_ISSUE(c + 2);
        CP_COMMIT();

        int buf = c % 3;
        uint32_t Ab = smA + buf * ASTAGE;
        uint32_t Bb = smB + buf * 16384;
#pragma unroll
        for (int ks = 0; ks < 4; ks++) {
            uint32_t af[MT][4], bf[2][4];
#pragma unroll
            for (int mt = 0; mt < MT; mt++) {
                int rA = rowAl + mt * 16;
                ldsm4(af[mt], Ab + (rA * 8 + ((2 * ks + cuA) ^ (rA & 7))) * 16);
            }
#pragma unroll
            for (int np = 0; np < 2; np++) {
                int rB = rowBl + np * 16;
                ldsm4(bf[np], Bb + (rB * 8 + ((2 * ks + cuB) ^ (rB & 7))) * 16);
            }
#pragma unroll
            for (int mt = 0; mt < MT; mt++)
#pragma unroll
                for (int nt = 0; nt < 4; nt++)
                    mma16(acc[mt][nt], af[mt], &bf[nt >> 1][(nt & 1) * 2]);
        }
    }

    int g = lane >> 2, tg = lane & 3;
    if (OUT32) {
        float* C = (float*)Cv;
#pragma unroll
        for (int mt = 0; mt < MT; mt++)
#pragma unroll
            for (int nt = 0; nt < 4; nt++)
#pragma unroll
                for (int half = 0; half < 2; half++) {
                    int row = m0 + wm * (BM / 2) + mt * 16 + g + half * 8;
                    int col = n0 + wn * 32 + nt * 8 + tg * 2;
                    float2 v = make_float2(acc[mt][nt][half * 2],
                                           acc[mt][nt][half * 2 + 1]);
                    *(float2*)&C[(size_t)row * DM + col] = v;
                }
    } else if (blockIdx.z == 2) {
        // V projection: write transposed fp16 into g_vt (bh, d, s)
#pragma unroll
        for (int mt = 0; mt < MT; mt++)
#pragma unroll
            for (int nt = 0; nt < 4; nt++)
#pragma unroll
                for (int half = 0; half < 2; half++) {
                    int row = m0 + wm * (BM / 2) + mt * 16 + g + half * 8;
                    int b = row >> 11, s = row & (SQ - 1);
                    int col = n0 + wn * 32 + nt * 8 + tg * 2;
                    int h = col >> 6, d = col & 63;
                    size_t base = ((size_t)((b * NH + h) * HD + d)) * SQ + s;
                    g_vt[base]      = __float2half(acc[mt][nt][half * 2]);
                    g_vt[base + SQ] = __float2half(acc[mt][nt][half * 2 + 1]);
                }
    } else {
        // q/k projection: fused 2D RoPE (+1/8 scale for q) in fp32, then fp16
        float scale = (blockIdx.z == 0) ? 0.125f : 1.0f;
        int halfIdx = wn & 1;    // warp n-tile == one 32-col rope half
#pragma unroll
        for (int mt = 0; mt < MT; mt++)
#pragma unroll
            for (int e = 0; e < 4; e++) {
                int row = m0 + wm * (BM / 2) + mt * 16 + g + (e >> 1) * 8;
                int s = row & (SQ - 1);
                const float2* tab = g_tab + s * 32 + halfIdx * 16;
#pragma unroll
                for (int nt = 0; nt < 2; nt++) {
                    int i = nt * 8 + tg * 2 + (e & 1);
                    float2 cs = tab[i];
                    float x1 = acc[mt][nt][e];
                    float x2 = acc[mt][nt + 2][e];
                    acc[mt][nt][e]     = (x1 * cs.x - x2 * cs.y) * scale;
                    acc[mt][nt + 2][e] = (x2 * cs.x + x1 * cs.y) * scale;
                }
            }
        __half* C = (__half*)Cv;
#pragma unroll
        for (int mt = 0; mt < MT; mt++)
#pragma unroll
            for (int nt = 0; nt < 4; nt++)
#pragma unroll
                for (int half = 0; half < 2; half++) {
                    int row = m0 + wm * (BM / 2) + mt * 16 + g + half * 8;
                    int col = n0 + wn * 32 + nt * 8 + tg * 2;
                    *(uint32_t*)&C[(size_t)row * DM + col] =
                        f22h2(acc[mt][nt][half * 2], acc[mt][nt][half * 2 + 1]);
                }
    }
#undef G_ISSUE
}

// ============================================================================
// Flash attention, fp16 mma m16n8k16. CTA: 64q x 64k, 4 warps (16 q each).
// cp.async double-buffered K/Vt; P C-frag -> A-frag by half2 packing (free).
// smem 40KB; target 4 CTA/SM (160KB smem, regs <= 128).
// ============================================================================
#define ATT_SMEM 40960

__global__ __launch_bounds__(128, 4) void attn_h() {
    extern __shared__ __align__(16) char smx[];
    uint32_t Qb    = smem_u32(smx);
    uint32_t Kbase = Qb + 8192;
    uint32_t Vbase = Qb + 24576;

    int tid = threadIdx.x, wid = tid >> 5, lane = tid & 31;
    int bx = blockIdx.x;
    int qt = (SQ / 64 - 1) - bx / (NB * NH);
    int bh = bx % (NB * NH);
    int b = bh / NH, h = bh % NH;

    const __half* Qg  = g_q + ((size_t)(b * SQ + qt * 64)) * DM + h * HD;
    const __half* Kg  = g_k + (size_t)b * SQ * DM + h * HD;
    const __half* Vtg = g_vt + (size_t)bh * HD * SQ;

    int nkt = qt + 1;

#define KV_ISSUE(t)                                                         \
    do {                                                                    \
        if ((t) < nkt) {                                                    \
            int _k0 = (t) * 64;                                             \
            uint32_t _ks = Kbase + ((t) & 1) * 8192;                        \
            uint32_t _vs = Vbase + ((t) & 1) * 8192;                        \
            _Pragma("unroll") for (int i = 0; i < 4; i++) {                 \
                int idx = tid + i * 128;                                    \
                int r = idx >> 3, u = idx & 7;                              \
                cp16(_ks + (r * 8 + (u ^ (r & 7))) * 16,                    \
                     Kg + (size_t)(_k0 + r) * DM + u * 8);                  \
                cp16(_vs + (r * 8 + (u ^ (r & 7))) * 16,                    \
                     Vtg + (size_t)r * SQ + _k0 + u * 8);                   \
            }                                                               \
        }                                                                   \
    } while (0)

    KV_ISSUE(0); CP_COMMIT();
    // Q tile via cp.async (already roped+scaled)
#pragma unroll
    for (int i = 0; i < 4; i++) {
        int idx = tid + i * 128;
        int r = idx >> 3, u = idx & 7;
        cp16(Qb + (r * 8 + (u ^ (r & 7))) * 16, Qg + (size_t)r * DM + u * 8);
    }
    CP_COMMIT();
    CP_WAIT(0);
    __syncthreads();

    int rowAl = wid * 16 + (lane & 15);
    int cuA   = lane >> 4;
    int rowBl = ((lane >> 4) * 8) + (lane & 7);
    int cuB   = (lane >> 3) & 1;
    int g = lane >> 2, tg = lane & 3;

    uint32_t aq[4][4];
#pragma unroll
    for (int ks = 0; ks < 4; ks++)
        ldsm4(aq[ks], Qb + (rowAl * 8 + ((2 * ks + cuA) ^ (rowAl & 7))) * 16);

    float o[8][4];
#pragma unroll
    for (int i = 0; i < 8; i++)
#pragma unroll
        for (int e = 0; e < 4; e++) o[i][e] = 0.0f;
    float m0r = -1e30f, m1r = -1e30f, l0 = 0.0f, l1 = 0.0f;

    int qwarp = qt * 64 + wid * 16;

    for (int t = 0; t < nkt; t++) {
        int k0 = t * 64;
        KV_ISSUE(t + 1); CP_COMMIT();

        uint32_t Kb = Kbase + (t & 1) * 8192;
        uint32_t Vb = Vbase + (t & 1) * 8192;

        float s[8][4];
#pragma unroll
        for (int i = 0; i < 8; i++)
#pragma unroll
            for (int e = 0; e < 4; e++) s[i][e] = 0.0f;

#pragma unroll
        for (int ks = 0; ks < 4; ks++) {
            uint32_t bk[4][4];
#pragma unroll
            for (int np = 0; np < 4; np++) {
                int rB = rowBl + np * 16;
                ldsm4(bk[np], Kb + (rB * 8 + ((2 * ks + cuB) ^ (rB & 7))) * 16);
            }
#pragma unroll
            for (int nt = 0; nt < 8; nt++)
                mma16(s[nt], aq[ks], &bk[nt >> 1][(nt & 1) * 2]);
        }

        if (k0 + 63 > qwarp) {
#pragma unroll
            for (int nt = 0; nt < 8; nt++)
#pragma unroll
                for (int e = 0; e < 4; e++) {
                    int colg = k0 + nt * 8 + tg * 2 + (e & 1);
                    int rowg = qwarp + g + (e >> 1) * 8;
                    if (colg > rowg) s[nt][e] = -1e30f;
                }
        }

        float rm0 = -1e30f, rm1 = -1e30f;
#pragma unroll
        for (int nt = 0; nt < 8; nt++) {
            rm0 = fmaxf(rm0, fmaxf(s[nt][0], s[nt][1]));
            rm1 = fmaxf(rm1, fmaxf(s[nt][2], s[nt][3]));
        }
        rm0 = fmaxf(rm0, __shfl_xor_sync(0xffffffffu, rm0, 1));
        rm0 = fmaxf(rm0, __shfl_xor_sync(0xffffffffu, rm0, 2));
        rm1 = fmaxf(rm1, __shfl_xor_sync(0xffffffffu, rm1, 1));
        rm1 = fmaxf(rm1, __shfl_xor_sync(0xffffffffu, rm1, 2));
        float mn0 = fmaxf(m0r, rm0), mn1 = fmaxf(m1r, rm1);
        float al0 = __expf(m0r - mn0), al1 = __expf(m1r - mn1);
        m0r = mn0; m1r = mn1;
        float rs0 = 0.0f, rs1 = 0.0f;
#pragma unroll
        for (int nt = 0; nt < 8; nt++) {
            s[nt][0] = __expf(s[nt][0] - mn0);
            s[nt][1] = __expf(s[nt][1] - mn0);
            s[nt][2] = __expf(s[nt][2] - mn1);
            s[nt][3] = __expf(s[nt][3] - mn1);
            rs0 += s[nt][0] + s[nt][1];
            rs1 += s[nt][2] + s[nt][3];
        }
        l0 = l0 * al0 + rs0;
        l1 = l1 * al1 + rs1;
#pragma unroll
        for (int nt = 0; nt < 8; nt++) {
            o[nt][0] *= al0; o[nt][1] *= al0;
            o[nt][2] *= al1; o[nt][3] *= al1;
        }

#pragma unroll
        for (int kb = 0; kb < 4; kb++) {
            uint32_t ap[4];
            ap[0] = f22h2(s[2 * kb][0],     s[2 * kb][1]);
            ap[1] = f22h2(s[2 * kb][2],     s[2 * kb][3]);
            ap[2] = f22h2(s[2 * kb + 1][0], s[2 * kb + 1][1]);
            ap[3] = f22h2(s[2 * kb + 1][2], s[2 * kb + 1][3]);
            uint32_t bv[4][4];
#pragma unroll
            for (int np = 0; np < 4; np++) {
                int rB = rowBl + np * 16;
                ldsm4(bv[np], Vb + (rB * 8 + ((2 * kb + cuB) ^ (rB & 7))) * 16);
            }
#pragma unroll
            for (int nt = 0; nt < 8; nt++)
                mma16(o[nt], ap, &bv[nt >> 1][(nt & 1) * 2]);
        }

        CP_WAIT(0);
        __syncthreads();
    }

    l0 += __shfl_xor_sync(0xffffffffu, l0, 1);
    l0 += __shfl_xor_sync(0xffffffffu, l0, 2);
    l1 += __shfl_xor_sync(0xffffffffu, l1, 1);
    l1 += __shfl_xor_sync(0xffffffffu, l1, 2);
    float inv0 = 1.0f / l0, inv1 = 1.0f / l1;

    __half* Og = g_attn + ((size_t)(b * SQ + qt * 64 + wid * 16)) * DM + h * HD;
#pragma unroll
    for (int nt = 0; nt < 8; nt++) {
        int col = nt * 8 + tg * 2;
        *(uint32_t*)&Og[(size_t)g * DM + col] =
            f22h2(o[nt][0] * inv0, o[nt][1] * inv0);
        *(uint32_t*)&Og[(size_t)(g + 8) * DM + col] =
            f22h2(o[nt][2] * inv1, o[nt][3] * inv1);
    }
#undef KV_ISSUE
}

// ---------------------------------------------------------------------------
extern "C" void kernel_launch(void* const* d_in, const int* in_sizes, int n_in,
                              void* d_out, int out_size) {
    const float* x  = (const float*)d_in[0];
    const int* row  = (const int*)d_in[1];
    const int* col  = (const int*)d_in[2];
    const float* Wq = (const float*)d_in[3];
    const float* Wk = (const float*)d_in[4];
    const float* Wv = (const float*)d_in[5];
    const float* Wo = (const float*)d_in[6];
    float* out = (float*)d_out;

    void *qp, *kp, *ap, *xp, *wqp, *wkp, *wvp, *wop;
    cudaGetSymbolAddress(&qp, g_q);
    cudaGetSymbolAddress(&kp, g_k);
    cudaGetSymbolAddress(&ap, g_attn);
    cudaGetSymbolAddress(&xp, g_x);
    cudaGetSymbolAddress(&wqp, g_wq);
    cudaGetSymbolAddress(&wkp, g_wk);
    cudaGetSymbolAddress(&wvp, g_wv);
    cudaGetSymbolAddress(&wop, g_wo);

    cudaFuncSetAttribute(gemm_h<128, false>,
                         cudaFuncAttributeMaxDynamicSharedMemorySize, 98304);
    cudaFuncSetAttribute(gemm_h<64, true>,
                         cudaFuncAttributeMaxDynamicSharedMemorySize, 73728);
    cudaFuncSetAttribute(attn_h,
                         cudaFuncAttributeMaxDynamicSharedMemorySize, ATT_SMEM);

    // 0) fused prep: x/W -> fp16, rope table (single launch)
    prep_kernel<<<XBLK + 4 * WBLK + TBLK, 256>>>(
        (const float4*)x, (const float4*)Wq, (const float4*)Wk,
        (const float4*)Wv, (const float4*)Wo, row, col,
        (uint2*)xp, (uint2*)wqp, (uint2*)wkp, (uint2*)wvp, (uint2*)wop);

    // 1) fused QKV projections + RoPE epilogue; z==2 writes V^T to g_vt
    gemm_h<128, false><<<dim3(DM / 128, (NB * SQ) / 128, 3), 256, 98304>>>(
        (const __half*)xp, (const __half*)wqp, (const __half*)wkp,
        (const __half*)wvp, qp, kp, nullptr);

    // 2) flash attention (fp16, heavy-first)
    attn_h<<<(SQ / 64) * NB * NH, 128, ATT_SMEM>>>();

    // 3) output projection (fp32 out)
    gemm_h<64, true><<<dim3(DM / 128, (NB * SQ) / 64, 1), 256, 73728>>>(
        (const __half*)ap, (const __half*)wop, (const __half*)wop,
        (const __half*)wop, out, out, out);
}

// round 9
// speedup vs baseline: 8.5748x; 1.0003x over previous
#include <cuda_runtime.h>
#include <cuda_fp16.h>
#include <cstdint>
#include <math.h>

#define NB 2
#define NH 12
#define SQ 2048
#define HD 64
#define DM 768

// ---------------- scratch (device globals; no allocations allowed) ----------
__device__ __half g_q[NB * SQ * DM];          // (B,S,H*D) fp16, roped+scaled
__device__ __half g_k[NB * SQ * DM];          // fp16, roped
__device__ __half g_vt[NB * NH * HD * SQ];    // (bh, d, s) fp16
__device__ __half g_attn[NB * SQ * DM];       // fp16 attn out
__device__ __half g_x[NB * SQ * DM];          // fp16 x
__device__ __half g_wq[DM * DM], g_wk[DM * DM], g_wv[DM * DM], g_wo[DM * DM];
__device__ float2 g_tab[SQ * 32];             // (s, half, i) -> (cos, sin)

// ============================ helpers =======================================
__device__ __forceinline__ uint32_t smem_u32(const void* p) {
    uint32_t a;
    asm("{ .reg .u64 t; cvta.to.shared.u64 t, %1; cvt.u32.u64 %0, t; }"
        : "=r"(a) : "l"(p));
    return a;
}
__device__ __forceinline__ uint32_t f22h2(float a, float b) {
    __half2 h = __floats2half2_rn(a, b);
    return *reinterpret_cast<uint32_t*>(&h);
}
__device__ __forceinline__ void ldsm4(uint32_t* r, uint32_t addr) {
    asm volatile("ldmatrix.sync.aligned.m8n8.x4.shared.b16 {%0,%1,%2,%3}, [%4];"
                 : "=r"(r[0]), "=r"(r[1]), "=r"(r[2]), "=r"(r[3]) : "r"(addr));
}
__device__ __forceinline__ void mma16(float* d, const uint32_t* a,
                                      const uint32_t* b) {
    asm volatile(
        "mma.sync.aligned.m16n8k16.row.col.f32.f16.f16.f32 "
        "{%0,%1,%2,%3}, {%4,%5,%6,%7}, {%8,%9}, {%0,%1,%2,%3};"
        : "+f"(d[0]), "+f"(d[1]), "+f"(d[2]), "+f"(d[3])
        : "r"(a[0]), "r"(a[1]), "r"(a[2]), "r"(a[3]), "r"(b[0]), "r"(b[1]));
}
__device__ __forceinline__ void cp16(uint32_t dst, const void* src) {
    asm volatile("cp.async.cg.shared.global [%0], [%1], 16;"
                 :: "r"(dst), "l"(src));
}
#define CP_COMMIT() asm volatile("cp.async.commit_group;" ::: "memory")
#define CP_WAIT(n)  asm volatile("cp.async.wait_group " #n ";" ::: "memory")

// ============================================================================
// Fused prep: x->fp16 | 4 weights->fp16 | rope table, one launch.
// ============================================================================
#define XBLK (NB * SQ * DM / 4 / 256)          // 3072
#define WBLK (DM * DM / 4 / 256)               // 576
#define TBLK (SQ * 32 / 256)                   // 256
__global__ void prep_kernel(const float4* __restrict__ x,
                            const float4* __restrict__ wq,
                            const float4* __restrict__ wk,
                            const float4* __restrict__ wv,
                            const float4* __restrict__ wo,
                            const int* __restrict__ row_ids,
                            const int* __restrict__ col_ids,
                            uint2* __restrict__ dx,
                            uint2* __restrict__ dwq, uint2* __restrict__ dwk,
                            uint2* __restrict__ dwv, uint2* __restrict__ dwo) {
    int blk = blockIdx.x;
    if (blk < XBLK) {
        int i = blk * 256 + threadIdx.x;
        float4 v = x[i];
        dx[i] = make_uint2(f22h2(v.x, v.y), f22h2(v.z, v.w));
    } else if (blk < XBLK + 4 * WBLK) {
        int w = (blk - XBLK) / WBLK;
        int i = ((blk - XBLK) % WBLK) * 256 + threadIdx.x;
        const float4* s = (w == 0) ? wq : (w == 1) ? wk : (w == 2) ? wv : wo;
        uint2* d        = (w == 0) ? dwq : (w == 1) ? dwk : (w == 2) ? dwv : dwo;
        float4 v = s[i];
        d[i] = make_uint2(f22h2(v.x, v.y), f22h2(v.z, v.w));
    } else {
        int idx = (blk - XBLK - 4 * WBLK) * 256 + threadIdx.x;   // < SQ*32
        int s = idx >> 5, p = idx & 31;
        int half = p >> 4, i = p & 15;
        int pos = (half == 0) ? row_ids[s] : col_ids[s];
        float inv = expf(-(float)i * (9.210340371976184f / 16.0f));
        float ang = (float)pos * inv;
        float c, sn;
        sincosf(ang, &sn, &c);
        g_tab[idx] = make_float2(c, sn);
    }
}

// ============================================================================
// fp16 GEMM: C = A(MxDM) @ W(DMxDM)^T. CTA tile BM x 128, BK=64, 128 thr
// (4 warps, 2x2), warp tile (BM/2) x 64. 3-stage cp.async, 1 barrier/chunk.
// 32 mma : 8 ldsm per ks (vs 16:6 before) + 256-reg budget -> ptxas can
// pipeline fragment loads against mma.
// OUT32: fp32 C. Else fp16 C with fused 2D-RoPE epilogue (z==0 q * 1/8,
// z==1 k); z==2 writes V transposed fp16 to g_vt.
// ============================================================================
template <int BM, bool OUT32>
__global__ __launch_bounds__(128, 2) void gemm_h(
    const __half* __restrict__ A,
    const __half* __restrict__ W0, const __half* __restrict__ W1,
    const __half* __restrict__ W2,
    void* __restrict__ C0v, void* __restrict__ C1v, void* __restrict__ C2v) {
    const __half* W = (blockIdx.z == 0) ? W0 : (blockIdx.z == 1) ? W1 : W2;
    void* Cv        = (blockIdx.z == 0) ? C0v : (blockIdx.z == 1) ? C1v : C2v;

    constexpr int MT = BM / 32;        // m-tiles per warp (16 rows each)
    constexpr int ASTAGE = BM * 128;   // bytes per A stage
    constexpr int NCH = DM / 64;       // 12 chunks

    extern __shared__ __align__(16) char smx[];
    uint32_t smA = smem_u32(smx);
    uint32_t smB = smA + 3 * ASTAGE;

    int tid = threadIdx.x, wid = tid >> 5, lane = tid & 31;
    int m0 = blockIdx.y * BM, n0 = blockIdx.x * 128;
    int wm = wid >> 1, wn = wid & 1;

    int rowAl = wm * (BM / 2) + (lane & 15);
    int cuA   = lane >> 4;
    int rowBl = wn * 64 + ((lane >> 4) * 8) + (lane & 7);
    int cuB   = (lane >> 3) & 1;

    const __half* Ag = A + (size_t)m0 * DM;
    const __half* Wg = W + (size_t)n0 * DM;

#define G_ISSUE(c)                                                          \
    do {                                                                    \
        int _buf = (c) % 3;                                                 \
        uint32_t _sa = smA + _buf * ASTAGE;                                 \
        uint32_t _sb = smB + _buf * 16384;                                  \
        _Pragma("unroll") for (int i = 0; i < BM / 16; i++) {               \
            int idx = tid + i * 128;                                        \
            int r = idx >> 3, u = idx & 7;                                  \
            cp16(_sa + (r * 8 + (u ^ (r & 7))) * 16,                        \
                 Ag + (size_t)r * DM + (c) * 64 + u * 8);                   \
        }                                                                   \
        _Pragma("unroll") for (int i = 0; i < 8; i++) {                     \
            int idx = tid + i * 128;                                        \
            int r = idx >> 3, u = idx & 7;                                  \
            cp16(_sb + (r * 8 + (u ^ (r & 7))) * 16,                        \
                 Wg + (size_t)r * DM + (c) * 64 + u * 8);                   \
        }                                                                   \
    } while (0)

    G_ISSUE(0); CP_COMMIT();
    G_ISSUE(1); CP_COMMIT();

    float acc[MT][8][4];
#pragma unroll
    for (int i = 0; i < MT; i++)
#pragma unroll
        for (int j = 0; j < 8; j++)
#pragma unroll
            for (int e = 0; e < 4; e++) acc[i][j][e] = 0.0f;

    for (int c = 0; c < NCH; c++) {
        CP_WAIT(1);
        __syncthreads();
        if (c + 2 < NCH) G_ISSUE(c + 2);
        CP_COMMIT();

        int buf = c % 3;
        uint32_t Ab = smA + buf * ASTAGE;
        uint32_t Bb = smB + buf * 16384;
#pragma unroll
        for (int ks = 0; ks < 4; ks++) {
            uint32_t af[MT][4], bf[4][4];
#pragma unroll
            for (int mt = 0; mt < MT; mt++) {
                int rA = rowAl + mt * 16;
                ldsm4(af[mt], Ab + (rA * 8 + ((2 * ks + cuA) ^ (rA & 7))) * 16);
            }
#pragma unroll
            for (int np = 0; np < 4; np++) {
                int rB = rowBl + np * 16;
                ldsm4(bf[np], Bb + (rB * 8 + ((2 * ks + cuB) ^ (rB & 7))) * 16);
            }
#pragma unroll
            for (int mt = 0; mt < MT; mt++)
#pragma unroll
                for (int nt = 0; nt < 8; nt++)
                    mma16(acc[mt][nt], af[mt], &bf[nt >> 1][(nt & 1) * 2]);
        }
    }

    int g = lane >> 2, tg = lane & 3;
    if (OUT32) {
        float* C = (float*)Cv;
#pragma unroll
        for (int mt = 0; mt < MT; mt++)
#pragma unroll
            for (int nt = 0; nt < 8; nt++)
#pragma unroll
                for (int half = 0; half < 2; half++) {
                    int row = m0 + wm * (BM / 2) + mt * 16 + g + half * 8;
                    int col = n0 + wn * 64 + nt * 8 + tg * 2;
                    float2 v = make_float2(acc[mt][nt][half * 2],
                                           acc[mt][nt][half * 2 + 1]);
                    *(float2*)&C[(size_t)row * DM + col] = v;
                }
    } else if (blockIdx.z == 2) {
        // V projection: write transposed fp16 into g_vt (bh, d, s)
#pragma unroll
        for (int mt = 0; mt < MT; mt++)
#pragma unroll
            for (int nt = 0; nt < 8; nt++)
#pragma unroll
                for (int half = 0; half < 2; half++) {
                    int row = m0 + wm * (BM / 2) + mt * 16 + g + half * 8;
                    int b = row >> 11, s = row & (SQ - 1);
                    int col = n0 + wn * 64 + nt * 8 + tg * 2;
                    int h = col >> 6, d = col & 63;
                    size_t base = ((size_t)((b * NH + h) * HD + d)) * SQ + s;
                    g_vt[base]      = __float2half(acc[mt][nt][half * 2]);
                    g_vt[base + SQ] = __float2half(acc[mt][nt][half * 2 + 1]);
                }
    } else {
        // q/k: fused 2D RoPE (+1/8 scale for q) in fp32, then fp16 store.
        // Warp n-range = 64 = one head. d = nt*8+tg*2+(e&1); half = nt>>2;
        // pair (d, d+16) == (nt, nt+2) within each group of 4 n-tiles.
        float scale = (blockIdx.z == 0) ? 0.125f : 1.0f;
#pragma unroll
        for (int mt = 0; mt < MT; mt++)
#pragma unroll
            for (int e = 0; e < 4; e++) {
                int row = m0 + wm * (BM / 2) + mt * 16 + g + (e >> 1) * 8;
                int s = row & (SQ - 1);
#pragma unroll
                for (int h2 = 0; h2 < 2; h2++) {
                    const float2* tab = g_tab + s * 32 + h2 * 16;
#pragma unroll
                    for (int nt0 = 0; nt0 < 2; nt0++) {
                        int nt = h2 * 4 + nt0;
                        int i = nt0 * 8 + tg * 2 + (e & 1);
                        float2 cs = tab[i];
                        float x1 = acc[mt][nt][e];
                        float x2 = acc[mt][nt + 2][e];
                        acc[mt][nt][e]     = (x1 * cs.x - x2 * cs.y) * scale;
                        acc[mt][nt + 2][e] = (x2 * cs.x + x1 * cs.y) * scale;
                    }
                }
            }
        __half* C = (__half*)Cv;
#pragma unroll
        for (int mt = 0; mt < MT; mt++)
#pragma unroll
            for (int nt = 0; nt < 8; nt++)
#pragma unroll
                for (int half = 0; half < 2; half++) {
                    int row = m0 + wm * (BM / 2) + mt * 16 + g + half * 8;
                    int col = n0 + wn * 64 + nt * 8 + tg * 2;
                    *(uint32_t*)&C[(size_t)row * DM + col] =
                        f22h2(acc[mt][nt][half * 2], acc[mt][nt][half * 2 + 1]);
                }
    }
#undef G_ISSUE
}

// ============================================================================
// Flash attention, fp16 mma m16n8k16. CTA: 64q x 64k, 4 warps (16 q each).
// cp.async double-buffered K/Vt; P C-frag -> A-frag by half2 packing (free).
// smem 40KB, 4 CTA/SM.
// ============================================================================
#define ATT_SMEM 40960

__global__ __launch_bounds__(128, 4) void attn_h() {
    extern __shared__ __align__(16) char smx[];
    uint32_t Qb    = smem_u32(smx);
    uint32_t Kbase = Qb + 8192;
    uint32_t Vbase = Qb + 24576;

    int tid = threadIdx.x, wid = tid >> 5, lane = tid & 31;
    int bx = blockIdx.x;
    int qt = (SQ / 64 - 1) - bx / (NB * NH);
    int bh = bx % (NB * NH);
    int b = bh / NH, h = bh % NH;

    const __half* Qg  = g_q + ((size_t)(b * SQ + qt * 64)) * DM + h * HD;
    const __half* Kg  = g_k + (size_t)b * SQ * DM + h * HD;
    const __half* Vtg = g_vt + (size_t)bh * HD * SQ;

    int nkt = qt + 1;

#define KV_ISSUE(t)                                                         \
    do {                                                                    \
        if ((t) < nkt) {                                                    \
            int _k0 = (t) * 64;                                             \
            uint32_t _ks = Kbase + ((t) & 1) * 8192;                        \
            uint32_t _vs = Vbase + ((t) & 1) * 8192;                        \
            _Pragma("unroll") for (int i = 0; i < 4; i++) {                 \
                int idx = tid + i * 128;                                    \
                int r = idx >> 3, u = idx & 7;                              \
                cp16(_ks + (r * 8 + (u ^ (r & 7))) * 16,                    \
                     Kg + (size_t)(_k0 + r) * DM + u * 8);                  \
                cp16(_vs + (r * 8 + (u ^ (r & 7))) * 16,                    \
                     Vtg + (size_t)r * SQ + _k0 + u * 8);                   \
            }                                                               \
        }                                                                   \
    } while (0)

    KV_ISSUE(0); CP_COMMIT();
#pragma unroll
    for (int i = 0; i < 4; i++) {
        int idx = tid + i * 128;
        int r = idx >> 3, u = idx & 7;
        cp16(Qb + (r * 8 + (u ^ (r & 7))) * 16, Qg + (size_t)r * DM + u * 8);
    }
    CP_COMMIT();
    CP_WAIT(0);
    __syncthreads();

    int rowAl = wid * 16 + (lane & 15);
    int cuA   = lane >> 4;
    int rowBl = ((lane >> 4) * 8) + (lane & 7);
    int cuB   = (lane >> 3) & 1;
    int g = lane >> 2, tg = lane & 3;

    uint32_t aq[4][4];
#pragma unroll
    for (int ks = 0; ks < 4; ks++)
        ldsm4(aq[ks], Qb + (rowAl * 8 + ((2 * ks + cuA) ^ (rowAl & 7))) * 16);

    float o[8][4];
#pragma unroll
    for (int i = 0; i < 8; i++)
#pragma unroll
        for (int e = 0; e < 4; e++) o[i][e] = 0.0f;
    float m0r = -1e30f, m1r = -1e30f, l0 = 0.0f, l1 = 0.0f;

    int qwarp = qt * 64 + wid * 16;

    for (int t = 0; t < nkt; t++) {
        int k0 = t * 64;
        KV_ISSUE(t + 1); CP_COMMIT();

        uint32_t Kb = Kbase + (t & 1) * 8192;
        uint32_t Vb = Vbase + (t & 1) * 8192;

        float s[8][4];
#pragma unroll
        for (int i = 0; i < 8; i++)
#pragma unroll
            for (int e = 0; e < 4; e++) s[i][e] = 0.0f;

#pragma unroll
        for (int ks = 0; ks < 4; ks++) {
            uint32_t bk[4][4];
#pragma unroll
            for (int np = 0; np < 4; np++) {
                int rB = rowBl + np * 16;
                ldsm4(bk[np], Kb + (rB * 8 + ((2 * ks + cuB) ^ (rB & 7))) * 16);
            }
#pragma unroll
            for (int nt = 0; nt < 8; nt++)
                mma16(s[nt], aq[ks], &bk[nt >> 1][(nt & 1) * 2]);
        }

        if (k0 + 63 > qwarp) {
#pragma unroll
            for (int nt = 0; nt < 8; nt++)
#pragma unroll
                for (int e = 0; e < 4; e++) {
                    int colg = k0 + nt * 8 + tg * 2 + (e & 1);
                    int rowg = qwarp + g + (e >> 1) * 8;
                    if (colg > rowg) s[nt][e] = -1e30f;
                }
        }

        float rm0 = -1e30f, rm1 = -1e30f;
#pragma unroll
        for (int nt = 0; nt < 8; nt++) {
            rm0 = fmaxf(rm0, fmaxf(s[nt][0], s[nt][1]));
            rm1 = fmaxf(rm1, fmaxf(s[nt][2], s[nt][3]));
        }
        rm0 = fmaxf(rm0, __shfl_xor_sync(0xffffffffu, rm0, 1));
        rm0 = fmaxf(rm0, __shfl_xor_sync(0xffffffffu, rm0, 2));
        rm1 = fmaxf(rm1, __shfl_xor_sync(0xffffffffu, rm1, 1));
        rm1 = fmaxf(rm1, __shfl_xor_sync(0xffffffffu, rm1, 2));
        float mn0 = fmaxf(m0r, rm0), mn1 = fmaxf(m1r, rm1);
        float al0 = __expf(m0r - mn0), al1 = __expf(m1r - mn1);
        m0r = mn0; m1r = mn1;
        float rs0 = 0.0f, rs1 = 0.0f;
#pragma unroll
        for (int nt = 0; nt < 8; nt++) {
            s[nt][0] = __expf(s[nt][0] - mn0);
            s[nt][1] = __expf(s[nt][1] - mn0);
            s[nt][2] = __expf(s[nt][2] - mn1);
            s[nt][3] = __expf(s[nt][3] - mn1);
            rs0 += s[nt][0] + s[nt][1];
            rs1 += s[nt][2] + s[nt][3];
        }
        l0 = l0 * al0 + rs0;
        l1 = l1 * al1 + rs1;
#pragma unroll
        for (int nt = 0; nt < 8; nt++) {
            o[nt][0] *= al0; o[nt][1] *= al0;
            o[nt][2] *= al1; o[nt][3] *= al1;
        }

#pragma unroll
        for (int kb = 0; kb < 4; kb++) {
            uint32_t ap[4];
            ap[0] = f22h2(s[2 * kb][0],     s[2 * kb][1]);
            ap[1] = f22h2(s[2 * kb][2],     s[2 * kb][3]);
            ap[2] = f22h2(s[2 * kb + 1][0], s[2 * kb + 1][1]);
            ap[3] = f22h2(s[2 * kb + 1][2], s[2 * kb + 1][3]);
            uint32_t bv[4][4];
#pragma unroll
            for (int np = 0; np < 4; np++) {
                int rB = rowBl + np * 16;
                ldsm4(bv[np], Vb + (rB * 8 + ((2 * kb + cuB) ^ (rB & 7))) * 16);
            }
#pragma unroll
            for (int nt = 0; nt < 8; nt++)
                mma16(o[nt], ap, &bv[nt >> 1][(nt & 1) * 2]);
        }

        CP_WAIT(0);
        __syncthreads();
    }

    l0 += __shfl_xor_sync(0xffffffffu, l0, 1);
    l0 += __shfl_xor_sync(0xffffffffu, l0, 2);
    l1 += __shfl_xor_sync(0xffffffffu, l1, 1);
    l1 += __shfl_xor_sync(0xffffffffu, l1, 2);
    float inv0 = 1.0f / l0, inv1 = 1.0f / l1;

    __half* Og = g_attn + ((size_t)(b * SQ + qt * 64 + wid * 16)) * DM + h * HD;
#pragma unroll
    for (int nt = 0; nt < 8; nt++) {
        int col = nt * 8 + tg * 2;
        *(uint32_t*)&Og[(size_t)g * DM + col] =
            f22h2(o[nt][0] * inv0, o[nt][1] * inv0);
        *(uint32_t*)&Og[(size_t)(g + 8) * DM + col] =
            f22h2(o[nt][2] * inv1, o[nt][3] * inv1);
    }
#undef KV_ISSUE
}

// ---------------------------------------------------------------------------
extern "C" void kernel_launch(void* const* d_in, const int* in_sizes, int n_in,
                              void* d_out, int out_size) {
    const float* x  = (const float*)d_in[0];
    const int* row  = (const int*)d_in[1];
    const int* col  = (const int*)d_in[2];
    const float* Wq = (const float*)d_in[3];
    const float* Wk = (const float*)d_in[4];
    const float* Wv = (const float*)d_in[5];
    const float* Wo = (const float*)d_in[6];
    float* out = (float*)d_out;

    void *qp, *kp, *ap, *xp, *wqp, *wkp, *wvp, *wop;
    cudaGetSymbolAddress(&qp, g_q);
    cudaGetSymbolAddress(&kp, g_k);
    cudaGetSymbolAddress(&ap, g_attn);
    cudaGetSymbolAddress(&xp, g_x);
    cudaGetSymbolAddress(&wqp, g_wq);
    cudaGetSymbolAddress(&wkp, g_wk);
    cudaGetSymbolAddress(&wvp, g_wv);
    cudaGetSymbolAddress(&wop, g_wo);

    cudaFuncSetAttribute(gemm_h<128, false>,
                         cudaFuncAttributeMaxDynamicSharedMemorySize, 98304);
    cudaFuncSetAttribute(gemm_h<64, true>,
                         cudaFuncAttributeMaxDynamicSharedMemorySize, 73728);
    cudaFuncSetAttribute(attn_h,
                         cudaFuncAttributeMaxDynamicSharedMemorySize, ATT_SMEM);

    // 0) fused prep: x/W -> fp16, rope table (single launch)
    prep_kernel<<<XBLK + 4 * WBLK + TBLK, 256>>>(
        (const float4*)x, (const float4*)Wq, (const float4*)Wk,
        (const float4*)Wv, (const float4*)Wo, row, col,
        (uint2*)xp, (uint2*)wqp, (uint2*)wkp, (uint2*)wvp, (uint2*)wop);

    // 1) fused QKV projections + RoPE epilogue; z==2 writes V^T to g_vt
    gemm_h<128, false><<<dim3(DM / 128, (NB * SQ) / 128, 3), 128, 98304>>>(
        (const __half*)xp, (const __half*)wqp, (const __half*)wkp,
        (const __half*)wvp, qp, kp, nullptr);

    // 2) flash attention (fp16, heavy-first)
    attn_h<<<(SQ / 64) * NB * NH, 128, ATT_SMEM>>>();

    // 3) output projection (fp32 out, BM=64 for wave balance)
    gemm_h<64, true><<<dim3(DM / 128, (NB * SQ) / 64, 1), 128, 73728>>>(
        (const __half*)ap, (const __half*)wop, (const __half*)wop,
        (const __half*)wop, out, out, out);
}

// round 10
// speedup vs baseline: 9.0326x; 1.0534x over previous
#include <cuda_runtime.h>
#include <cuda_fp16.h>
#include <cstdint>
#include <math.h>

#define NB 2
#define NH 12
#define SQ 2048
#define HD 64
#define DM 768

// ---------------- scratch (device globals; no allocations allowed) ----------
__device__ __half g_q[NB * SQ * DM];          // (B,S,H*D) fp16, roped+scaled
__device__ __half g_k[NB * SQ * DM];          // fp16, roped
__device__ __half g_vt[NB * NH * HD * SQ];    // (bh, d, s) fp16
__device__ __half g_attn[NB * SQ * DM];       // fp16 attn out
__device__ __half g_x[NB * SQ * DM];          // fp16 x
__device__ __half g_wq[DM * DM], g_wk[DM * DM], g_wv[DM * DM], g_wo[DM * DM];
__device__ float2 g_tab[SQ * 32];             // (s, half, i) -> (cos, sin)

// ============================ helpers =======================================
__device__ __forceinline__ uint32_t smem_u32(const void* p) {
    uint32_t a;
    asm("{ .reg .u64 t; cvta.to.shared.u64 t, %1; cvt.u32.u64 %0, t; }"
        : "=r"(a) : "l"(p));
    return a;
}
__device__ __forceinline__ uint32_t f22h2(float a, float b) {
    __half2 h = __floats2half2_rn(a, b);
    return *reinterpret_cast<uint32_t*>(&h);
}
__device__ __forceinline__ void ldsm4(uint32_t* r, uint32_t addr) {
    asm volatile("ldmatrix.sync.aligned.m8n8.x4.shared.b16 {%0,%1,%2,%3}, [%4];"
                 : "=r"(r[0]), "=r"(r[1]), "=r"(r[2]), "=r"(r[3]) : "r"(addr));
}
__device__ __forceinline__ void mma16(float* d, const uint32_t* a,
                                      const uint32_t* b) {
    asm volatile(
        "mma.sync.aligned.m16n8k16.row.col.f32.f16.f16.f32 "
        "{%0,%1,%2,%3}, {%4,%5,%6,%7}, {%8,%9}, {%0,%1,%2,%3};"
        : "+f"(d[0]), "+f"(d[1]), "+f"(d[2]), "+f"(d[3])
        : "r"(a[0]), "r"(a[1]), "r"(a[2]), "r"(a[3]), "r"(b[0]), "r"(b[1]));
}
__device__ __forceinline__ void cp16(uint32_t dst, const void* src) {
    asm volatile("cp.async.cg.shared.global [%0], [%1], 16;"
                 :: "r"(dst), "l"(src));
}
#define CP_COMMIT() asm volatile("cp.async.commit_group;" ::: "memory")
#define CP_WAIT(n)  asm volatile("cp.async.wait_group " #n ";" ::: "memory")

// ============================================================================
// Fused prep: x->fp16 | 4 weights->fp16 | rope table, one launch.
// ============================================================================
#define XBLK (NB * SQ * DM / 4 / 256)          // 3072
#define WBLK (DM * DM / 4 / 256)               // 576
#define TBLK (SQ * 32 / 256)                   // 256
__global__ void prep_kernel(const float4* __restrict__ x,
                            const float4* __restrict__ wq,
                            const float4* __restrict__ wk,
                            const float4* __restrict__ wv,
                            const float4* __restrict__ wo,
                            const int* __restrict__ row_ids,
                            const int* __restrict__ col_ids,
                            uint2* __restrict__ dx,
                            uint2* __restrict__ dwq, uint2* __restrict__ dwk,
                            uint2* __restrict__ dwv, uint2* __restrict__ dwo) {
    int blk = blockIdx.x;
    if (blk < XBLK) {
        int i = blk * 256 + threadIdx.x;
        float4 v = x[i];
        dx[i] = make_uint2(f22h2(v.x, v.y), f22h2(v.z, v.w));
    } else if (blk < XBLK + 4 * WBLK) {
        int w = (blk - XBLK) / WBLK;
        int i = ((blk - XBLK) % WBLK) * 256 + threadIdx.x;
        const float4* s = (w == 0) ? wq : (w == 1) ? wk : (w == 2) ? wv : wo;
        uint2* d        = (w == 0) ? dwq : (w == 1) ? dwk : (w == 2) ? dwv : dwo;
        float4 v = s[i];
        d[i] = make_uint2(f22h2(v.x, v.y), f22h2(v.z, v.w));
    } else {
        int idx = (blk - XBLK - 4 * WBLK) * 256 + threadIdx.x;   // < SQ*32
        int s = idx >> 5, p = idx & 31;
        int half = p >> 4, i = p & 15;
        int pos = (half == 0) ? row_ids[s] : col_ids[s];
        float inv = expf(-(float)i * (9.210340371976184f / 16.0f));
        float ang = (float)pos * inv;
        float c, sn;
        sincosf(ang, &sn, &c);
        g_tab[idx] = make_float2(c, sn);
    }
}

// ============================================================================
// fp16 GEMM: C = A(MxDM) @ W(DMxDM)^T. CTA tile BM x 128, BK=64, 128 thr
// (4 warps, 2x2), warp tile (BM/2) x 64. 3-stage cp.async, 1 barrier/chunk.
// EXPLICIT fragment double-buffering (manual 2x unroll) so every MMA group
// issues from resident registers: LD0 LD1 M0 LD2 M1 LD3 M2 M3.
// OUT32: fp32 C. Else fp16 C with fused 2D-RoPE epilogue (z==0 q * 1/8,
// z==1 k); z==2 writes V transposed fp16 to g_vt.
// ============================================================================
template <int BM, bool OUT32>
__global__ __launch_bounds__(128, 2) void gemm_h(
    const __half* __restrict__ A,
    const __half* __restrict__ W0, const __half* __restrict__ W1,
    const __half* __restrict__ W2,
    void* __restrict__ C0v, void* __restrict__ C1v, void* __restrict__ C2v) {
    const __half* W = (blockIdx.z == 0) ? W0 : (blockIdx.z == 1) ? W1 : W2;
    void* Cv        = (blockIdx.z == 0) ? C0v : (blockIdx.z == 1) ? C1v : C2v;

    constexpr int MT = BM / 32;        // m-tiles per warp (16 rows each)
    constexpr int ASTAGE = BM * 128;   // bytes per A stage
    constexpr int NCH = DM / 64;       // 12 chunks

    extern __shared__ __align__(16) char smx[];
    uint32_t smA = smem_u32(smx);
    uint32_t smB = smA + 3 * ASTAGE;

    int tid = threadIdx.x, wid = tid >> 5, lane = tid & 31;
    int m0 = blockIdx.y * BM, n0 = blockIdx.x * 128;
    int wm = wid >> 1, wn = wid & 1;

    int rowAl = wm * (BM / 2) + (lane & 15);
    int cuA   = lane >> 4;
    int rowBl = wn * 64 + ((lane >> 4) * 8) + (lane & 7);
    int cuB   = (lane >> 3) & 1;

    const __half* Ag = A + (size_t)m0 * DM;
    const __half* Wg = W + (size_t)n0 * DM;

#define G_ISSUE(c)                                                          \
    do {                                                                    \
        int _buf = (c) % 3;                                                 \
        uint32_t _sa = smA + _buf * ASTAGE;                                 \
        uint32_t _sb = smB + _buf * 16384;                                  \
        _Pragma("unroll") for (int i = 0; i < BM / 16; i++) {               \
            int idx = tid + i * 128;                                        \
            int r = idx >> 3, u = idx & 7;                                  \
            cp16(_sa + (r * 8 + (u ^ (r & 7))) * 16,                        \
                 Ag + (size_t)r * DM + (c) * 64 + u * 8);                   \
        }                                                                   \
        _Pragma("unroll") for (int i = 0; i < 8; i++) {                     \
            int idx = tid + i * 128;                                        \
            int r = idx >> 3, u = idx & 7;                                  \
            cp16(_sb + (r * 8 + (u ^ (r & 7))) * 16,                        \
                 Wg + (size_t)r * DM + (c) * 64 + u * 8);                   \
        }                                                                   \
    } while (0)

#define LD_FRAG(af, bf, ks)                                                 \
    do {                                                                    \
        _Pragma("unroll") for (int mt = 0; mt < MT; mt++) {                 \
            int rA = rowAl + mt * 16;                                       \
            ldsm4(af[mt], Ab + (rA * 8 + ((2 * (ks) + cuA) ^ (rA & 7))) * 16); \
        }                                                                   \
        _Pragma("unroll") for (int np = 0; np < 4; np++) {                  \
            int rB = rowBl + np * 16;                                       \
            ldsm4(bf[np], Bb + (rB * 8 + ((2 * (ks) + cuB) ^ (rB & 7))) * 16); \
        }                                                                   \
    } while (0)

#define MMA_FRAG(af, bf)                                                    \
    do {                                                                    \
        _Pragma("unroll") for (int mt = 0; mt < MT; mt++)                   \
            _Pragma("unroll") for (int nt = 0; nt < 8; nt++)                \
                mma16(acc[mt][nt], af[mt], &bf[nt >> 1][(nt & 1) * 2]);     \
    } while (0)

    G_ISSUE(0); CP_COMMIT();
    G_ISSUE(1); CP_COMMIT();

    float acc[MT][8][4];
#pragma unroll
    for (int i = 0; i < MT; i++)
#pragma unroll
        for (int j = 0; j < 8; j++)
#pragma unroll
            for (int e = 0; e < 4; e++) acc[i][j][e] = 0.0f;

    uint32_t afA[MT][4], bfA[4][4], afB[MT][4], bfB[4][4];

    for (int c = 0; c < NCH; c++) {
        CP_WAIT(1);
        __syncthreads();
        if (c + 2 < NCH) G_ISSUE(c + 2);
        CP_COMMIT();

        int buf = c % 3;
        uint32_t Ab = smA + buf * ASTAGE;
        uint32_t Bb = smB + buf * 16384;

        LD_FRAG(afA, bfA, 0);
        LD_FRAG(afB, bfB, 1);
        MMA_FRAG(afA, bfA);
        LD_FRAG(afA, bfA, 2);
        MMA_FRAG(afB, bfB);
        LD_FRAG(afB, bfB, 3);
        MMA_FRAG(afA, bfA);
        MMA_FRAG(afB, bfB);
    }

    int g = lane >> 2, tg = lane & 3;
    if (OUT32) {
        float* C = (float*)Cv;
#pragma unroll
        for (int mt = 0; mt < MT; mt++)
#pragma unroll
            for (int nt = 0; nt < 8; nt++)
#pragma unroll
                for (int half = 0; half < 2; half++) {
                    int row = m0 + wm * (BM / 2) + mt * 16 + g + half * 8;
                    int col = n0 + wn * 64 + nt * 8 + tg * 2;
                    float2 v = make_float2(acc[mt][nt][half * 2],
                                           acc[mt][nt][half * 2 + 1]);
                    *(float2*)&C[(size_t)row * DM + col] = v;
                }
    } else if (blockIdx.z == 2) {
        // V projection: write transposed fp16 into g_vt (bh, d, s)
#pragma unroll
        for (int mt = 0; mt < MT; mt++)
#pragma unroll
            for (int nt = 0; nt < 8; nt++)
#pragma unroll
                for (int half = 0; half < 2; half++) {
                    int row = m0 + wm * (BM / 2) + mt * 16 + g + half * 8;
                    int b = row >> 11, s = row & (SQ - 1);
                    int col = n0 + wn * 64 + nt * 8 + tg * 2;
                    int h = col >> 6, d = col & 63;
                    size_t base = ((size_t)((b * NH + h) * HD + d)) * SQ + s;
                    g_vt[base]      = __float2half(acc[mt][nt][half * 2]);
                    g_vt[base + SQ] = __float2half(acc[mt][nt][half * 2 + 1]);
                }
    } else {
        // q/k: fused 2D RoPE (+1/8 scale for q) in fp32, then fp16 store.
        float scale = (blockIdx.z == 0) ? 0.125f : 1.0f;
#pragma unroll
        for (int mt = 0; mt < MT; mt++)
#pragma unroll
            for (int e = 0; e < 4; e++) {
                int row = m0 + wm * (BM / 2) + mt * 16 + g + (e >> 1) * 8;
                int s = row & (SQ - 1);
#pragma unroll
                for (int h2 = 0; h2 < 2; h2++) {
                    const float2* tab = g_tab + s * 32 + h2 * 16;
#pragma unroll
                    for (int nt0 = 0; nt0 < 2; nt0++) {
                        int nt = h2 * 4 + nt0;
                        int i = nt0 * 8 + tg * 2 + (e & 1);
                        float2 cs = tab[i];
                        float x1 = acc[mt][nt][e];
                        float x2 = acc[mt][nt + 2][e];
                        acc[mt][nt][e]     = (x1 * cs.x - x2 * cs.y) * scale;
                        acc[mt][nt + 2][e] = (x2 * cs.x + x1 * cs.y) * scale;
                    }
                }
            }
        __half* C = (__half*)Cv;
#pragma unroll
        for (int mt = 0; mt < MT; mt++)
#pragma unroll
            for (int nt = 0; nt < 8; nt++)
#pragma unroll
                for (int half = 0; half < 2; half++) {
                    int row = m0 + wm * (BM / 2) + mt * 16 + g + half * 8;
                    int col = n0 + wn * 64 + nt * 8 + tg * 2;
                    *(uint32_t*)&C[(size_t)row * DM + col] =
                        f22h2(acc[mt][nt][half * 2], acc[mt][nt][half * 2 + 1]);
                }
    }
#undef G_ISSUE
#undef LD_FRAG
#undef MMA_FRAG
}

// ============================================================================
// Flash attention, fp16 mma m16n8k16. CTA: 64q x 64k, 4 warps (16 q each).
// 3 CTA/SM (reg cap 170) so the V fragments for PV can be hoisted ABOVE the
// softmax: their ldsm latency hides under the exp/shfl chain.
// ============================================================================
#define ATT_SMEM 40960

__global__ __launch_bounds__(128, 3) void attn_h() {
    extern __shared__ __align__(16) char smx[];
    uint32_t Qb    = smem_u32(smx);
    uint32_t Kbase = Qb + 8192;
    uint32_t Vbase = Qb + 24576;

    int tid = threadIdx.x, wid = tid >> 5, lane = tid & 31;
    int bx = blockIdx.x;
    int qt = (SQ / 64 - 1) - bx / (NB * NH);
    int bh = bx % (NB * NH);
    int b = bh / NH, h = bh % NH;

    const __half* Qg  = g_q + ((size_t)(b * SQ + qt * 64)) * DM + h * HD;
    const __half* Kg  = g_k + (size_t)b * SQ * DM + h * HD;
    const __half* Vtg = g_vt + (size_t)bh * HD * SQ;

    int nkt = qt + 1;

#define KV_ISSUE(t)                                                         \
    do {                                                                    \
        if ((t) < nkt) {                                                    \
            int _k0 = (t) * 64;                                             \
            uint32_t _ks = Kbase + ((t) & 1) * 8192;                        \
            uint32_t _vs = Vbase + ((t) & 1) * 8192;                        \
            _Pragma("unroll") for (int i = 0; i < 4; i++) {                 \
                int idx = tid + i * 128;                                    \
                int r = idx >> 3, u = idx & 7;                              \
                cp16(_ks + (r * 8 + (u ^ (r & 7))) * 16,                    \
                     Kg + (size_t)(_k0 + r) * DM + u * 8);                  \
                cp16(_vs + (r * 8 + (u ^ (r & 7))) * 16,                    \
                     Vtg + (size_t)r * SQ + _k0 + u * 8);                   \
            }                                                               \
        }                                                                   \
    } while (0)

#define LDV(bv, kb)                                                         \
    do {                                                                    \
        _Pragma("unroll") for (int np = 0; np < 4; np++) {                  \
            int rB = rowBl + np * 16;                                       \
            ldsm4(bv[np], Vb + (rB * 8 + ((2 * (kb) + cuB) ^ (rB & 7))) * 16); \
        }                                                                   \
    } while (0)

#define PV_MMA(kb, bv)                                                      \
    do {                                                                    \
        uint32_t ap[4];                                                     \
        ap[0] = f22h2(s[2 * (kb)][0],     s[2 * (kb)][1]);                  \
        ap[1] = f22h2(s[2 * (kb)][2],     s[2 * (kb)][3]);                  \
        ap[2] = f22h2(s[2 * (kb) + 1][0], s[2 * (kb) + 1][1]);              \
        ap[3] = f22h2(s[2 * (kb) + 1][2], s[2 * (kb) + 1][3]);              \
        _Pragma("unroll") for (int nt = 0; nt < 8; nt++)                    \
            mma16(o[nt], ap, &bv[nt >> 1][(nt & 1) * 2]);                   \
    } while (0)

    KV_ISSUE(0); CP_COMMIT();
#pragma unroll
    for (int i = 0; i < 4; i++) {
        int idx = tid + i * 128;
        int r = idx >> 3, u = idx & 7;
        cp16(Qb + (r * 8 + (u ^ (r & 7))) * 16, Qg + (size_t)r * DM + u * 8);
    }
    CP_COMMIT();
    CP_WAIT(0);
    __syncthreads();

    int rowAl = wid * 16 + (lane & 15);
    int cuA   = lane >> 4;
    int rowBl = ((lane >> 4) * 8) + (lane & 7);
    int cuB   = (lane >> 3) & 1;
    int g = lane >> 2, tg = lane & 3;

    uint32_t aq[4][4];
#pragma unroll
    for (int ks = 0; ks < 4; ks++)
        ldsm4(aq[ks], Qb + (rowAl * 8 + ((2 * ks + cuA) ^ (rowAl & 7))) * 16);

    float o[8][4];
#pragma unroll
    for (int i = 0; i < 8; i++)
#pragma unroll
        for (int e = 0; e < 4; e++) o[i][e] = 0.0f;
    float m0r = -1e30f, m1r = -1e30f, l0 = 0.0f, l1 = 0.0f;

    int qwarp = qt * 64 + wid * 16;

    for (int t = 0; t < nkt; t++) {
        int k0 = t * 64;
        KV_ISSUE(t + 1); CP_COMMIT();

        uint32_t Kb = Kbase + (t & 1) * 8192;
        uint32_t Vb = Vbase + (t & 1) * 8192;

        float s[8][4];
#pragma unroll
        for (int i = 0; i < 8; i++)
#pragma unroll
            for (int e = 0; e < 4; e++) s[i][e] = 0.0f;

#pragma unroll
        for (int ks = 0; ks < 4; ks++) {
            uint32_t bk[4][4];
#pragma unroll
            for (int np = 0; np < 4; np++) {
                int rB = rowBl + np * 16;
                ldsm4(bk[np], Kb + (rB * 8 + ((2 * ks + cuB) ^ (rB & 7))) * 16);
            }
#pragma unroll
            for (int nt = 0; nt < 8; nt++)
                mma16(s[nt], aq[ks], &bk[nt >> 1][(nt & 1) * 2]);
        }

        // hoist V fragments for kb 0,1 above softmax — latency hidden by exp
        uint32_t bvA[4][4], bvB[4][4];
        LDV(bvA, 0);
        LDV(bvB, 1);

        if (k0 + 63 > qwarp) {
#pragma unroll
            for (int nt = 0; nt < 8; nt++)
#pragma unroll
                for (int e = 0; e < 4; e++) {
                    int colg = k0 + nt * 8 + tg * 2 + (e & 1);
                    int rowg = qwarp + g + (e >> 1) * 8;
                    if (colg > rowg) s[nt][e] = -1e30f;
                }
        }

        float rm0 = -1e30f, rm1 = -1e30f;
#pragma unroll
        for (int nt = 0; nt < 8; nt++) {
            rm0 = fmaxf(rm0, fmaxf(s[nt][0], s[nt][1]));
            rm1 = fmaxf(rm1, fmaxf(s[nt][2], s[nt][3]));
        }
        rm0 = fmaxf(rm0, __shfl_xor_sync(0xffffffffu, rm0, 1));
        rm0 = fmaxf(rm0, __shfl_xor_sync(0xffffffffu, rm0, 2));
        rm1 = fmaxf(rm1, __shfl_xor_sync(0xffffffffu, rm1, 1));
        rm1 = fmaxf(rm1, __shfl_xor_sync(0xffffffffu, rm1, 2));
        float mn0 = fmaxf(m0r, rm0), mn1 = fmaxf(m1r, rm1);
        float al0 = __expf(m0r - mn0), al1 = __expf(m1r - mn1);
        m0r = mn0; m1r = mn1;
        float rs0 = 0.0f, rs1 = 0.0f;
#pragma unroll
        for (int nt = 0; nt < 8; nt++) {
            s[nt][0] = __expf(s[nt][0] - mn0);
            s[nt][1] = __expf(s[nt][1] - mn0);
            s[nt][2] = __expf(s[nt][2] - mn1);
            s[nt][3] = __expf(s[nt][3] - mn1);
            rs0 += s[nt][0] + s[nt][1];
            rs1 += s[nt][2] + s[nt][3];
        }
        l0 = l0 * al0 + rs0;
        l1 = l1 * al1 + rs1;
#pragma unroll
        for (int nt = 0; nt < 8; nt++) {
            o[nt][0] *= al0; o[nt][1] *= al0;
            o[nt][2] *= al1; o[nt][3] *= al1;
        }

        // PV with double-buffered V fragments
        PV_MMA(0, bvA);
        LDV(bvA, 2);
        PV_MMA(1, bvB);
        LDV(bvB, 3);
        PV_MMA(2, bvA);
        PV_MMA(3, bvB);

        CP_WAIT(0);
        __syncthreads();
    }

    l0 += __shfl_xor_sync(0xffffffffu, l0, 1);
    l0 += __shfl_xor_sync(0xffffffffu, l0, 2);
    l1 += __shfl_xor_sync(0xffffffffu, l1, 1);
    l1 += __shfl_xor_sync(0xffffffffu, l1, 2);
    float inv0 = 1.0f / l0, inv1 = 1.0f / l1;

    __half* Og = g_attn + ((size_t)(b * SQ + qt * 64 + wid * 16)) * DM + h * HD;
#pragma unroll
    for (int nt = 0; nt < 8; nt++) {
        int col = nt * 8 + tg * 2;
        *(uint32_t*)&Og[(size_t)g * DM + col] =
            f22h2(o[nt][0] * inv0, o[nt][1] * inv0);
        *(uint32_t*)&Og[(size_t)(g + 8) * DM + col] =
            f22h2(o[nt][2] * inv1, o[nt][3] * inv1);
    }
#undef KV_ISSUE
#undef LDV
#undef PV_MMA
}

// ---------------------------------------------------------------------------
extern "C" void kernel_launch(void* const* d_in, const int* in_sizes, int n_in,
                              void* d_out, int out_size) {
    const float* x  = (const float*)d_in[0];
    const int* row  = (const int*)d_in[1];
    const int* col  = (const int*)d_in[2];
    const float* Wq = (const float*)d_in[3];
    const float* Wk = (const float*)d_in[4];
    const float* Wv = (const float*)d_in[5];
    const float* Wo = (const float*)d_in[6];
    float* out = (float*)d_out;

    void *qp, *kp, *ap, *xp, *wqp, *wkp, *wvp, *wop;
    cudaGetSymbolAddress(&qp, g_q);
    cudaGetSymbolAddress(&kp, g_k);
    cudaGetSymbolAddress(&ap, g_attn);
    cudaGetSymbolAddress(&xp, g_x);
    cudaGetSymbolAddress(&wqp, g_wq);
    cudaGetSymbolAddress(&wkp, g_wk);
    cudaGetSymbolAddress(&wvp, g_wv);
    cudaGetSymbolAddress(&wop, g_wo);

    cudaFuncSetAttribute(gemm_h<128, false>,
                         cudaFuncAttributeMaxDynamicSharedMemorySize, 98304);
    cudaFuncSetAttribute(gemm_h<64, true>,
                         cudaFuncAttributeMaxDynamicSharedMemorySize, 73728);
    cudaFuncSetAttribute(attn_h,
                         cudaFuncAttributeMaxDynamicSharedMemorySize, ATT_SMEM);

    // 0) fused prep: x/W -> fp16, rope table (single launch)
    prep_kernel<<<XBLK + 4 * WBLK + TBLK, 256>>>(
        (const float4*)x, (const float4*)Wq, (const float4*)Wk,
        (const float4*)Wv, (const float4*)Wo, row, col,
        (uint2*)xp, (uint2*)wqp, (uint2*)wkp, (uint2*)wvp, (uint2*)wop);

    // 1) fused QKV projections + RoPE epilogue; z==2 writes V^T to g_vt
    gemm_h<128, false><<<dim3(DM / 128, (NB * SQ) / 128, 3), 128, 98304>>>(
        (const __half*)xp, (const __half*)wqp, (const __half*)wkp,
        (const __half*)wvp, qp, kp, nullptr);

    // 2) flash attention (fp16, heavy-first)
    attn_h<<<(SQ / 64) * NB * NH, 128, ATT_SMEM>>>();

    // 3) output projection (fp32 out, BM=64 for wave balance)
    gemm_h<64, true><<<dim3(DM / 128, (NB * SQ) / 64, 1), 128, 73728>>>(
        (const __half*)ap, (const __half*)wop, (const __half*)wop,
        (const __half*)wop, out, out, out);
}